// round 1
// baseline (speedup 1.0000x reference)
#include <cuda_runtime.h>
#include <math.h>

// Problem dims (fixed by reference)
#define BB 4
#define TT 2048
#define EE 1024
#define HH 16
#define DD 64
static __device__ __constant__ float kScale = 0.125f; // 1/sqrt(64)

// Scratch (allocation is banned; use __device__ globals)
__device__ float g_qkv[(size_t)BB * TT * 3 * EE]; // [B,T,3E]
__device__ float g_y[(size_t)BB * TT * EE];       // [B,T,E]

// ---------------------------------------------------------------------------
// Tiled fp32 GEMM with bias: C[M,N] = A[M,K] @ W[K,N] + bias[N]
// 64x64 block tile, BK=16, 256 threads, 4x4 micro-tile per thread.
// M,N,K all multiples of 64/16 here; no bounds checks.
// ---------------------------------------------------------------------------
__global__ __launch_bounds__(256) void gemm_bias_kernel(
    const float* __restrict__ A, const float* __restrict__ W,
    const float* __restrict__ bias, float* __restrict__ C,
    int M, int N, int K)
{
    __shared__ float As[16][64]; // [k][m]
    __shared__ float Bs[16][64]; // [k][n]

    const int tid = threadIdx.x;
    const int tr = tid >> 4;      // 0..15 (m micro-tile)
    const int tc = tid & 15;      // 0..15 (n micro-tile)
    const int m0 = blockIdx.y * 64;
    const int n0 = blockIdx.x * 64;

    // A-tile load mapping: 64 rows x 4 float4s
    const int ar  = tid >> 2;          // 0..63
    const int ac4 = (tid & 3) << 2;    // 0,4,8,12
    // B-tile load mapping: 16 rows x 16 float4s
    const int br  = tid >> 4;          // 0..15
    const int bc4 = (tid & 15) << 2;   // 0..60

    float acc[4][4] = {};

    for (int k0 = 0; k0 < K; k0 += 16) {
        float4 av = *(const float4*)(A + (size_t)(m0 + ar) * K + k0 + ac4);
        As[ac4 + 0][ar] = av.x;
        As[ac4 + 1][ar] = av.y;
        As[ac4 + 2][ar] = av.z;
        As[ac4 + 3][ar] = av.w;
        *(float4*)&Bs[br][bc4] =
            *(const float4*)(W + (size_t)(k0 + br) * N + n0 + bc4);
        __syncthreads();

#pragma unroll
        for (int k = 0; k < 16; ++k) {
            float4 a4 = *(const float4*)&As[k][tr << 2];
            float4 b4 = *(const float4*)&Bs[k][tc << 2];
            float a[4] = {a4.x, a4.y, a4.z, a4.w};
            float b[4] = {b4.x, b4.y, b4.z, b4.w};
#pragma unroll
            for (int i = 0; i < 4; ++i)
#pragma unroll
                for (int j = 0; j < 4; ++j)
                    acc[i][j] += a[i] * b[j];
        }
        __syncthreads();
    }

    const int col = n0 + (tc << 2);
    float4 bv = *(const float4*)(bias + col);
#pragma unroll
    for (int i = 0; i < 4; ++i) {
        int row = m0 + (tr << 2) + i;
        float4 o;
        o.x = acc[i][0] + bv.x;
        o.y = acc[i][1] + bv.y;
        o.z = acc[i][2] + bv.z;
        o.w = acc[i][3] + bv.w;
        *(float4*)(C + (size_t)row * N + col) = o;
    }
}

// ---------------------------------------------------------------------------
// Flash-attention (causal) per (query-block=64, head, batch).
// Key blocks of 32, online softmax, O accumulated in registers.
// Thread grid 16x16: S-phase each thread owns 4 rows x 2 key-cols,
// O-phase each thread owns 4 rows x 4 d-cols.
// ---------------------------------------------------------------------------
__global__ __launch_bounds__(256) void attn_kernel(
    const float* __restrict__ qkv, float* __restrict__ y)
{
    __shared__ float Qs[64][64]; // [d][m]   (transposed)
    __shared__ float Ks[64][32]; // [d][n]   (transposed)
    __shared__ float Vs[32][64]; // [n][d]   (natural)
    __shared__ float Ps[64][32]; // [m][n]

    const int qb = blockIdx.x;
    const int h  = blockIdx.y;
    const int b  = blockIdx.z;
    const int q0 = qb * 64;
    const int tid = threadIdx.x;
    const int tr = tid >> 4;   // 0..15
    const int tc = tid & 15;   // 0..15

    const size_t rowstride = (size_t)3 * EE;
    const float* qbase = qkv + (size_t)(b * TT) * rowstride + h * DD;

    // Load Q block [64 rows][64 d] -> Qs[d][m]
    for (int f = tid; f < 1024; f += 256) {
        int m  = f >> 4;
        int d4 = (f & 15) << 2;
        float4 v = *(const float4*)(qbase + (size_t)(q0 + m) * rowstride + d4);
        Qs[d4 + 0][m] = v.x;
        Qs[d4 + 1][m] = v.y;
        Qs[d4 + 2][m] = v.z;
        Qs[d4 + 3][m] = v.w;
    }

    float m_i[4], l_i[4], o[4][4];
#pragma unroll
    for (int i = 0; i < 4; ++i) {
        m_i[i] = -INFINITY;
        l_i[i] = 0.f;
#pragma unroll
        for (int j = 0; j < 4; ++j) o[i][j] = 0.f;
    }
    __syncthreads();

    const int nkb = (q0 >> 5) + 2; // key blocks of 32 covering keys <= q0+63

    for (int kb = 0; kb < nkb; ++kb) {
        const int k0 = kb * 32;

        // Load K block -> Ks[d][n], V block -> Vs[n][d]
        for (int f = tid; f < 512; f += 256) {
            int n  = f >> 4;
            int d4 = (f & 15) << 2;
            const float* kp = qbase + (size_t)(k0 + n) * rowstride + EE + d4;
            float4 kv = *(const float4*)kp;
            Ks[d4 + 0][n] = kv.x;
            Ks[d4 + 1][n] = kv.y;
            Ks[d4 + 2][n] = kv.z;
            Ks[d4 + 3][n] = kv.w;
            const float* vp = qbase + (size_t)(k0 + n) * rowstride + 2 * EE + d4;
            *(float4*)&Vs[n][d4] = *(const float4*)vp;
        }
        __syncthreads();

        // S = scale * Q K^T  (4 rows x 2 cols per thread)
        float s[4][2] = {};
#pragma unroll 8
        for (int d = 0; d < 64; ++d) {
            float4 a4 = *(const float4*)&Qs[d][tr << 2];
            float b0 = Ks[d][2 * tc + 0];
            float b1 = Ks[d][2 * tc + 1];
            s[0][0] += a4.x * b0; s[0][1] += a4.x * b1;
            s[1][0] += a4.y * b0; s[1][1] += a4.y * b1;
            s[2][0] += a4.z * b0; s[2][1] += a4.z * b1;
            s[3][0] += a4.w * b0; s[3][1] += a4.w * b1;
        }

        // scale + causal mask
#pragma unroll
        for (int i = 0; i < 4; ++i) {
            int qg = q0 + (tr << 2) + i;
#pragma unroll
            for (int j = 0; j < 2; ++j) {
                int kg = k0 + 2 * tc + j;
                s[i][j] = (kg <= qg) ? s[i][j] * kScale : -1e30f;
            }
        }

        // Online softmax per row (reduce across the 16 tc-threads, width-16 shfl)
#pragma unroll
        for (int i = 0; i < 4; ++i) {
            float rmax = fmaxf(s[i][0], s[i][1]);
#pragma unroll
            for (int off = 1; off < 16; off <<= 1)
                rmax = fmaxf(rmax, __shfl_xor_sync(0xffffffffu, rmax, off, 16));
            float mn = fmaxf(m_i[i], rmax);
            float c  = __expf(m_i[i] - mn);
            m_i[i] = mn;

            float p0 = __expf(s[i][0] - mn);
            float p1 = __expf(s[i][1] - mn);
            float rsum = p0 + p1;
#pragma unroll
            for (int off = 1; off < 16; off <<= 1)
                rsum += __shfl_xor_sync(0xffffffffu, rsum, off, 16);
            l_i[i] = l_i[i] * c + rsum;
#pragma unroll
            for (int j = 0; j < 4; ++j) o[i][j] *= c;

            Ps[(tr << 2) + i][2 * tc + 0] = p0;
            Ps[(tr << 2) + i][2 * tc + 1] = p1;
        }
        __syncthreads();

        // O += P @ V  (4 rows x 4 d-cols per thread)
#pragma unroll 4
        for (int j = 0; j < 32; ++j) {
            float4 v4 = *(const float4*)&Vs[j][tc << 2];
#pragma unroll
            for (int i = 0; i < 4; ++i) {
                float pv = Ps[(tr << 2) + i][j];
                o[i][0] += pv * v4.x;
                o[i][1] += pv * v4.y;
                o[i][2] += pv * v4.z;
                o[i][3] += pv * v4.w;
            }
        }
        __syncthreads();
    }

    // Normalize and write y[b, q0+m, h*D + d]
#pragma unroll
    for (int i = 0; i < 4; ++i) {
        float inv = 1.0f / l_i[i];
        int row = q0 + (tr << 2) + i;
        float4 ov;
        ov.x = o[i][0] * inv;
        ov.y = o[i][1] * inv;
        ov.z = o[i][2] * inv;
        ov.w = o[i][3] * inv;
        *(float4*)(y + (size_t)(b * TT + row) * EE + h * DD + (tc << 2)) = ov;
    }
}

// ---------------------------------------------------------------------------
// Launch
// ---------------------------------------------------------------------------
extern "C" void kernel_launch(void* const* d_in, const int* in_sizes, int n_in,
                              void* d_out, int out_size)
{
    const float* x     = (const float*)d_in[0];
    const float* Wqkv  = (const float*)d_in[1];
    const float* bqkv  = (const float*)d_in[2];
    const float* Wproj = (const float*)d_in[3];
    const float* bproj = (const float*)d_in[4];
    float* out = (float*)d_out;

    float *qkv, *y;
    cudaGetSymbolAddress((void**)&qkv, g_qkv);
    cudaGetSymbolAddress((void**)&y, g_y);

    const int M = BB * TT;

    // 1) QKV projection: [M,E] @ [E,3E] + b
    gemm_bias_kernel<<<dim3(3 * EE / 64, M / 64), 256>>>(
        x, Wqkv, bqkv, qkv, M, 3 * EE, EE);

    // 2) Causal flash attention
    attn_kernel<<<dim3(TT / 64, HH, BB), 256>>>(qkv, y);

    // 3) Output projection: [M,E] @ [E,E] + b
    gemm_bias_kernel<<<dim3(EE / 64, M / 64), 256>>>(
        y, Wproj, bproj, out, M, EE, EE);
}

// round 2
// speedup vs baseline: 1.2101x; 1.2101x over previous
#include <cuda_runtime.h>
#include <math.h>

// Problem dims (fixed by reference)
#define BB 4
#define TT 2048
#define EE 1024
#define HH 16
#define DD 64

// Scratch (allocation is banned; use __device__ globals)
__device__ float g_qkv[(size_t)BB * TT * 3 * EE]; // [B,T,3E]
__device__ float g_y[(size_t)BB * TT * EE];       // [B,T,E]

// ---------------------------------------------------------------------------
// GEMM v2: C[M,N] = A[M,K] @ W[K,N] + bias[N]
// 128x128 block tile, BK=16, 256 threads, 8x8 micro-tile (2x4 + 2x4 split),
// double-buffered smem, one __syncthreads per k-tile.
// ---------------------------------------------------------------------------
__global__ __launch_bounds__(256) void gemm_bias_v2(
    const float* __restrict__ A, const float* __restrict__ W,
    const float* __restrict__ bias, float* __restrict__ C,
    int M, int N, int K)
{
    __shared__ float As[2][16][132]; // [k][m], +4 pad for transpose-store
    __shared__ float Bs[2][16][128]; // [k][n]

    const int tid = threadIdx.x;
    const int tr = tid >> 4;   // 0..15
    const int tc = tid & 15;   // 0..15
    const int m0 = blockIdx.y << 7;
    const int n0 = blockIdx.x << 7;

    const float* Ap = A + (size_t)m0 * K;
    const float* Wp = W + n0;

    // Prologue: load k-tile 0 into buffer 0.
#pragma unroll
    for (int i = 0; i < 2; ++i) {
        int idx = tid + (i << 8);
        int ar = idx >> 2, ac = (idx & 3) << 2;
        float4 v = *(const float4*)(Ap + (size_t)ar * K + ac);
        As[0][ac + 0][ar] = v.x;
        As[0][ac + 1][ar] = v.y;
        As[0][ac + 2][ar] = v.z;
        As[0][ac + 3][ar] = v.w;
        int br = idx >> 5, bc = (idx & 31) << 2;
        *(float4*)&Bs[0][br][bc] = *(const float4*)(Wp + (size_t)br * N + bc);
    }
    __syncthreads();

    float acc[8][8] = {};
    float4 aReg[2], bReg[2];

    const int nT = K >> 4;
    for (int t = 0; t < nT; ++t) {
        const int cur = t & 1;
        const bool more = (t + 1 < nT);
        if (more) {
            const int k0 = (t + 1) << 4;
#pragma unroll
            for (int i = 0; i < 2; ++i) {
                int idx = tid + (i << 8);
                int ar = idx >> 2, ac = (idx & 3) << 2;
                aReg[i] = *(const float4*)(Ap + (size_t)ar * K + k0 + ac);
                int br = idx >> 5, bc = (idx & 31) << 2;
                bReg[i] = *(const float4*)(Wp + (size_t)(k0 + br) * N + bc);
            }
        }

#pragma unroll
        for (int k = 0; k < 16; ++k) {
            float a[8], b[8];
            *(float4*)&a[0] = *(const float4*)&As[cur][k][tr << 2];
            *(float4*)&a[4] = *(const float4*)&As[cur][k][(tr << 2) + 64];
            *(float4*)&b[0] = *(const float4*)&Bs[cur][k][tc << 2];
            *(float4*)&b[4] = *(const float4*)&Bs[cur][k][(tc << 2) + 64];
#pragma unroll
            for (int i = 0; i < 8; ++i)
#pragma unroll
                for (int j = 0; j < 8; ++j)
                    acc[i][j] += a[i] * b[j];
        }

        if (more) {
            const int nxt = cur ^ 1;
#pragma unroll
            for (int i = 0; i < 2; ++i) {
                int idx = tid + (i << 8);
                int ar = idx >> 2, ac = (idx & 3) << 2;
                As[nxt][ac + 0][ar] = aReg[i].x;
                As[nxt][ac + 1][ar] = aReg[i].y;
                As[nxt][ac + 2][ar] = aReg[i].z;
                As[nxt][ac + 3][ar] = aReg[i].w;
                int br = idx >> 5, bc = (idx & 31) << 2;
                *(float4*)&Bs[nxt][br][bc] = bReg[i];
            }
            __syncthreads();
        }
    }

    // Epilogue: + bias, write 8x8
    const float4 bv0 = *(const float4*)(bias + n0 + (tc << 2));
    const float4 bv1 = *(const float4*)(bias + n0 + (tc << 2) + 64);
#pragma unroll
    for (int ii = 0; ii < 2; ++ii) {
#pragma unroll
        for (int i = 0; i < 4; ++i) {
            const int row = m0 + (tr << 2) + i + (ii << 6);
            float4 o0, o1;
            o0.x = acc[ii * 4 + i][0] + bv0.x;
            o0.y = acc[ii * 4 + i][1] + bv0.y;
            o0.z = acc[ii * 4 + i][2] + bv0.z;
            o0.w = acc[ii * 4 + i][3] + bv0.w;
            o1.x = acc[ii * 4 + i][4] + bv1.x;
            o1.y = acc[ii * 4 + i][5] + bv1.y;
            o1.z = acc[ii * 4 + i][6] + bv1.z;
            o1.w = acc[ii * 4 + i][7] + bv1.w;
            *(float4*)(C + (size_t)row * N + n0 + (tc << 2)) = o0;
            *(float4*)(C + (size_t)row * N + n0 + (tc << 2) + 64) = o1;
        }
    }
}

// ---------------------------------------------------------------------------
// Flash-attention v2 (causal). 64 queries x 64 keys per tile, 256 threads.
// Thread (tr,tc): S-phase owns 4 rows x 4 key-cols; P exchanged via
// width-16 shfl (each row-group of 16 threads is intra-warp), so PV needs
// no P smem round-trip. O: 4 rows x 4 d-cols.
// ---------------------------------------------------------------------------
__global__ __launch_bounds__(256) void attn_kernel_v2(
    const float* __restrict__ qkv, float* __restrict__ y)
{
    __shared__ float Qs[64][64]; // [d][m]
    __shared__ float Ks[64][64]; // [d][n]
    __shared__ float Vs[64][64]; // [n][d]

    const int qb = blockIdx.x;
    const int h  = blockIdx.y;
    const int b  = blockIdx.z;
    const int q0 = qb << 6;
    const int tid = threadIdx.x;
    const int tr = tid >> 4;   // 0..15 (row group)
    const int tc = tid & 15;   // 0..15 (col group)

    const size_t rowstride = (size_t)3 * EE;
    const float* qbase = qkv + (size_t)(b * TT) * rowstride + h * DD;

    // Load Q block [64 rows][64 d] -> Qs[d][m]
    for (int f = tid; f < 1024; f += 256) {
        int m  = f >> 4;
        int d4 = (f & 15) << 2;
        float4 v = *(const float4*)(qbase + (size_t)(q0 + m) * rowstride + d4);
        Qs[d4 + 0][m] = v.x;
        Qs[d4 + 1][m] = v.y;
        Qs[d4 + 2][m] = v.z;
        Qs[d4 + 3][m] = v.w;
    }

    float m_i[4], l_i[4], o[4][4];
#pragma unroll
    for (int i = 0; i < 4; ++i) {
        m_i[i] = -INFINITY;
        l_i[i] = 0.f;
#pragma unroll
        for (int j = 0; j < 4; ++j) o[i][j] = 0.f;
    }

    const int nkb = (q0 >> 6) + 1; // 64-wide key tiles covering keys <= q0+63

    for (int kb = 0; kb < nkb; ++kb) {
        const int k0 = kb << 6;

        // Load K -> Ks[d][n] (transposed), V -> Vs[n][d] (natural)
        for (int f = tid; f < 1024; f += 256) {
            int n  = f >> 4;
            int d4 = (f & 15) << 2;
            const float* kp = qbase + (size_t)(k0 + n) * rowstride + EE + d4;
            float4 kv = *(const float4*)kp;
            Ks[d4 + 0][n] = kv.x;
            Ks[d4 + 1][n] = kv.y;
            Ks[d4 + 2][n] = kv.z;
            Ks[d4 + 3][n] = kv.w;
            const float* vp = qbase + (size_t)(k0 + n) * rowstride + 2 * EE + d4;
            *(float4*)&Vs[n][d4] = *(const float4*)vp;
        }
        __syncthreads();

        // S = Q K^T : 4 rows x 4 cols per thread
        float s[4][4] = {};
#pragma unroll 8
        for (int d = 0; d < 64; ++d) {
            float4 a4 = *(const float4*)&Qs[d][tr << 2];
            float4 b4 = *(const float4*)&Ks[d][tc << 2];
            float a[4] = {a4.x, a4.y, a4.z, a4.w};
            float bq[4] = {b4.x, b4.y, b4.z, b4.w};
#pragma unroll
            for (int i = 0; i < 4; ++i)
#pragma unroll
                for (int j = 0; j < 4; ++j)
                    s[i][j] += a[i] * bq[j];
        }

        // scale + causal mask (only the diagonal tile needs masking)
        const bool diag = (kb == nkb - 1);
#pragma unroll
        for (int i = 0; i < 4; ++i) {
            const int qi = (tr << 2) + i;
#pragma unroll
            for (int j = 0; j < 4; ++j) {
                const int kj = (tc << 2) + j;
                float v = s[i][j] * 0.125f;
                s[i][j] = (!diag || (kj <= qi)) ? v : -1e30f;
            }
        }

        // Online softmax per row; p := exp(s - m_new) stored back into s
#pragma unroll
        for (int i = 0; i < 4; ++i) {
            float rmax = fmaxf(fmaxf(s[i][0], s[i][1]), fmaxf(s[i][2], s[i][3]));
#pragma unroll
            for (int off = 1; off < 16; off <<= 1)
                rmax = fmaxf(rmax, __shfl_xor_sync(0xffffffffu, rmax, off, 16));
            const float mn = fmaxf(m_i[i], rmax);
            const float c  = __expf(m_i[i] - mn);
            m_i[i] = mn;

            float rsum = 0.f;
#pragma unroll
            for (int j = 0; j < 4; ++j) {
                s[i][j] = __expf(s[i][j] - mn);
                rsum += s[i][j];
            }
#pragma unroll
            for (int off = 1; off < 16; off <<= 1)
                rsum += __shfl_xor_sync(0xffffffffu, rsum, off, 16);
            l_i[i] = l_i[i] * c + rsum;
#pragma unroll
            for (int j = 0; j < 4; ++j) o[i][j] *= c;
        }

        // O += P @ V : P values fetched from owning lane via width-16 shfl
#pragma unroll
        for (int j = 0; j < 64; ++j) {
            const int src = j >> 2;   // lane within 16-group owning col j
            const int jj  = j & 3;    // compile-time after unroll
            float4 v4 = *(const float4*)&Vs[j][tc << 2];
            float p0 = __shfl_sync(0xffffffffu, s[0][jj], src, 16);
            float p1 = __shfl_sync(0xffffffffu, s[1][jj], src, 16);
            float p2 = __shfl_sync(0xffffffffu, s[2][jj], src, 16);
            float p3 = __shfl_sync(0xffffffffu, s[3][jj], src, 16);
            o[0][0] += p0 * v4.x; o[0][1] += p0 * v4.y; o[0][2] += p0 * v4.z; o[0][3] += p0 * v4.w;
            o[1][0] += p1 * v4.x; o[1][1] += p1 * v4.y; o[1][2] += p1 * v4.z; o[1][3] += p1 * v4.w;
            o[2][0] += p2 * v4.x; o[2][1] += p2 * v4.y; o[2][2] += p2 * v4.z; o[2][3] += p2 * v4.w;
            o[3][0] += p3 * v4.x; o[3][1] += p3 * v4.y; o[3][2] += p3 * v4.z; o[3][3] += p3 * v4.w;
        }
        __syncthreads(); // protect Ks/Vs before next tile load
    }

    // Normalize and write y[b, q0+row, h*D + tc*4]
#pragma unroll
    for (int i = 0; i < 4; ++i) {
        const float inv = 1.0f / l_i[i];
        const int row = q0 + (tr << 2) + i;
        float4 ov;
        ov.x = o[i][0] * inv;
        ov.y = o[i][1] * inv;
        ov.z = o[i][2] * inv;
        ov.w = o[i][3] * inv;
        *(float4*)(y + (size_t)(b * TT + row) * EE + h * DD + (tc << 2)) = ov;
    }
}

// ---------------------------------------------------------------------------
// Launch
// ---------------------------------------------------------------------------
extern "C" void kernel_launch(void* const* d_in, const int* in_sizes, int n_in,
                              void* d_out, int out_size)
{
    const float* x     = (const float*)d_in[0];
    const float* Wqkv  = (const float*)d_in[1];
    const float* bqkv  = (const float*)d_in[2];
    const float* Wproj = (const float*)d_in[3];
    const float* bproj = (const float*)d_in[4];
    float* out = (float*)d_out;

    float *qkv, *y;
    cudaGetSymbolAddress((void**)&qkv, g_qkv);
    cudaGetSymbolAddress((void**)&y, g_y);

    const int M = BB * TT;

    // 1) QKV projection: [M,E] @ [E,3E] + b
    gemm_bias_v2<<<dim3(3 * EE / 128, M / 128), 256>>>(
        x, Wqkv, bqkv, qkv, M, 3 * EE, EE);

    // 2) Causal flash attention
    attn_kernel_v2<<<dim3(TT / 64, HH, BB), 256>>>(qkv, y);

    // 3) Output projection: [M,E] @ [E,E] + b
    gemm_bias_v2<<<dim3(EE / 128, M / 128), 256>>>(
        y, Wproj, bproj, out, M, EE, EE);
}

// round 4
// speedup vs baseline: 1.6966x; 1.4020x over previous
#include <cuda_runtime.h>
#include <math.h>
#include <stdint.h>

// Problem dims (fixed by reference)
#define BB 4
#define TT 2048
#define EE 1024
#define HH 16
#define DD 64

// Scratch (allocation is banned; use __device__ globals)
__device__ float g_qkv[(size_t)BB * TT * 3 * EE];   // [B,T,3E]
__device__ float g_y[(size_t)BB * TT * EE];         // [B,T,E]
__device__ float g_wqkvT[(size_t)3 * EE * EE];      // [3E, E]  (W_qkv^T, K-major)
__device__ float g_wprojT[(size_t)EE * EE];         // [E, E]   (W_proj^T, K-major)

__device__ __forceinline__ uint32_t f2tf32(float f) {
    uint32_t r;
    asm("cvt.rna.tf32.f32 %0, %1;" : "=r"(r) : "f"(f));
    return r;
}

__device__ __forceinline__ void mma_tf32(float c[4], uint32_t a0, uint32_t a1,
                                         uint32_t a2, uint32_t a3,
                                         uint32_t b0, uint32_t b1) {
    asm volatile(
        "mma.sync.aligned.m16n8k8.row.col.f32.tf32.tf32.f32 "
        "{%0,%1,%2,%3}, {%4,%5,%6,%7}, {%8,%9}, {%0,%1,%2,%3};"
        : "+f"(c[0]), "+f"(c[1]), "+f"(c[2]), "+f"(c[3])
        : "r"(a0), "r"(a1), "r"(a2), "r"(a3), "r"(b0), "r"(b1));
}

// ---------------------------------------------------------------------------
// Transpose: out[c][r] = in[r][c], R x C, both multiples of 32
// ---------------------------------------------------------------------------
__global__ __launch_bounds__(256) void transpose_kernel(
    const float* __restrict__ in, float* __restrict__ out, int R, int C)
{
    __shared__ float t[32][33];
    int x = blockIdx.x * 32 + threadIdx.x;
    int y = blockIdx.y * 32 + threadIdx.y;
#pragma unroll
    for (int j = 0; j < 32; j += 8)
        t[threadIdx.y + j][threadIdx.x] = in[(size_t)(y + j) * C + x];
    __syncthreads();
    x = blockIdx.y * 32 + threadIdx.x;
    y = blockIdx.x * 32 + threadIdx.y;
#pragma unroll
    for (int j = 0; j < 32; j += 8)
        out[(size_t)(y + j) * R + x] = t[threadIdx.x][threadIdx.y + j];
}

// ---------------------------------------------------------------------------
// mma.sync tf32 GEMM: C[M,N] = A[M,K] @ Bt[N,K]^T + bias[N]
// 128x128 CTA tile, 8 warps (2m x 4n), warp tile 64x32 = 4x4 m16n8k8 tiles.
// Smem: A[128][32] and Bt[128][32], both K-major, stride 36 (conflict-free
// fragment loads), double-buffered, register prefetch of next k-tile.
// ---------------------------------------------------------------------------
#define SMS 36                      // smem row stride (floats)
#define TILE_F (128 * SMS)          // floats per (buf, matrix) tile
#define GEMM_SMEM_BYTES (2 * 2 * TILE_F * 4)

__global__ __launch_bounds__(256) void gemm_mma_tf32(
    const float* __restrict__ A, const float* __restrict__ Bt,
    const float* __restrict__ bias, float* __restrict__ C,
    int M, int N, int K)
{
    extern __shared__ float smem[];
    float* As = smem;               // [2][128][SMS]
    float* Bs = smem + 2 * TILE_F;  // [2][128][SMS]

    const int tid  = threadIdx.x;
    const int wid  = tid >> 5;
    const int lane = tid & 31;
    const int wm   = wid >> 2;      // 0..1
    const int wn   = wid & 3;       // 0..3
    const int r1   = lane >> 2;     // 0..7
    const int cg   = lane & 3;      // 0..3
    const int m0   = blockIdx.y << 7;
    const int n0   = blockIdx.x << 7;

    const float* Ap  = A  + (size_t)m0 * K;
    const float* Btp = Bt + (size_t)n0 * K;

    // load indices: 256 threads x 4 iters cover 128 rows x 8 float4 (32 floats)
    const int lr  = tid >> 3;          // row step base (0..31), +32 per iter
    const int lc4 = (tid & 7) << 2;    // float col 0..28

    // Prologue: tile 0 -> buffer 0
#pragma unroll
    for (int i = 0; i < 4; ++i) {
        const int r = lr + (i << 5);
        float4 va = *(const float4*)(Ap  + (size_t)r * K + lc4);
        float4 vb = *(const float4*)(Btp + (size_t)r * K + lc4);
        uint4 ua = make_uint4(f2tf32(va.x), f2tf32(va.y), f2tf32(va.z), f2tf32(va.w));
        uint4 ub = make_uint4(f2tf32(vb.x), f2tf32(vb.y), f2tf32(vb.z), f2tf32(vb.w));
        *(uint4*)(As + r * SMS + lc4) = ua;
        *(uint4*)(Bs + r * SMS + lc4) = ub;
    }
    __syncthreads();

    float acc[4][4][4] = {};
    float4 aR[4], bR[4];

    const int nT = K >> 5;
    for (int t = 0; t < nT; ++t) {
        const int buf = t & 1;
        const bool more = (t + 1 < nT);
        if (more) {
            const int k0 = (t + 1) << 5;
#pragma unroll
            for (int i = 0; i < 4; ++i) {
                const int r = lr + (i << 5);
                aR[i] = *(const float4*)(Ap  + (size_t)r * K + k0 + lc4);
                bR[i] = *(const float4*)(Btp + (size_t)r * K + k0 + lc4);
            }
        }

        const float* Ab = As + buf * TILE_F;
        const float* Bb = Bs + buf * TILE_F;
#pragma unroll
        for (int ks = 0; ks < 4; ++ks) {
            const int kk = ks << 3;
            uint32_t bf[4][2];
#pragma unroll
            for (int nt = 0; nt < 4; ++nt) {
                const float* p = Bb + (wn * 32 + nt * 8 + r1) * SMS + kk + cg;
                bf[nt][0] = __float_as_uint(p[0]);
                bf[nt][1] = __float_as_uint(p[4]);
            }
#pragma unroll
            for (int mt = 0; mt < 4; ++mt) {
                const float* p = Ab + (wm * 64 + mt * 16 + r1) * SMS + kk + cg;
                uint32_t a0 = __float_as_uint(p[0]);
                uint32_t a1 = __float_as_uint(p[8 * SMS]);
                uint32_t a2 = __float_as_uint(p[4]);
                uint32_t a3 = __float_as_uint(p[8 * SMS + 4]);
#pragma unroll
                for (int nt = 0; nt < 4; ++nt)
                    mma_tf32(acc[mt][nt], a0, a1, a2, a3, bf[nt][0], bf[nt][1]);
            }
        }

        if (more) {
            const int nxt = (t + 1) & 1;
            __syncthreads();
#pragma unroll
            for (int i = 0; i < 4; ++i) {
                const int r = lr + (i << 5);
                uint4 ua = make_uint4(f2tf32(aR[i].x), f2tf32(aR[i].y),
                                      f2tf32(aR[i].z), f2tf32(aR[i].w));
                uint4 ub = make_uint4(f2tf32(bR[i].x), f2tf32(bR[i].y),
                                      f2tf32(bR[i].z), f2tf32(bR[i].w));
                *(uint4*)(As + nxt * TILE_F + r * SMS + lc4) = ua;
                *(uint4*)(Bs + nxt * TILE_F + r * SMS + lc4) = ub;
            }
            __syncthreads();
        }
    }

    // Epilogue: + bias, write. acc[mt][nt]: rows r1/r1+8, cols 2cg, 2cg+1.
#pragma unroll
    for (int mt = 0; mt < 4; ++mt) {
#pragma unroll
        for (int nt = 0; nt < 4; ++nt) {
            const int row = m0 + wm * 64 + mt * 16 + r1;
            const int col = n0 + wn * 32 + nt * 8 + 2 * cg;
            const float2 bv = *(const float2*)(bias + col);
            float2 o0, o1;
            o0.x = acc[mt][nt][0] + bv.x;
            o0.y = acc[mt][nt][1] + bv.y;
            o1.x = acc[mt][nt][2] + bv.x;
            o1.y = acc[mt][nt][3] + bv.y;
            *(float2*)(C + (size_t)row * N + col) = o0;
            *(float2*)(C + (size_t)(row + 8) * N + col) = o1;
        }
    }
}

// ---------------------------------------------------------------------------
// Flash-attention v2 (causal). 64x64 tiles, 256 threads, P via width-16 shfl.
// (unchanged from round 2)
// ---------------------------------------------------------------------------
__global__ __launch_bounds__(256) void attn_kernel_v2(
    const float* __restrict__ qkv, float* __restrict__ y)
{
    __shared__ float Qs[64][64]; // [d][m]
    __shared__ float Ks[64][64]; // [d][n]
    __shared__ float Vs[64][64]; // [n][d]

    const int q0 = blockIdx.x << 6;
    const int h  = blockIdx.y;
    const int b  = blockIdx.z;
    const int tid = threadIdx.x;
    const int tr = tid >> 4;
    const int tc = tid & 15;

    const size_t rowstride = (size_t)3 * EE;
    const float* qbase = qkv + (size_t)(b * TT) * rowstride + h * DD;

    for (int f = tid; f < 1024; f += 256) {
        int m  = f >> 4;
        int d4 = (f & 15) << 2;
        float4 v = *(const float4*)(qbase + (size_t)(q0 + m) * rowstride + d4);
        Qs[d4 + 0][m] = v.x;
        Qs[d4 + 1][m] = v.y;
        Qs[d4 + 2][m] = v.z;
        Qs[d4 + 3][m] = v.w;
    }

    float m_i[4], l_i[4], o[4][4];
#pragma unroll
    for (int i = 0; i < 4; ++i) {
        m_i[i] = -INFINITY;
        l_i[i] = 0.f;
#pragma unroll
        for (int j = 0; j < 4; ++j) o[i][j] = 0.f;
    }

    const int nkb = (q0 >> 6) + 1;

    for (int kb = 0; kb < nkb; ++kb) {
        const int k0 = kb << 6;

        for (int f = tid; f < 1024; f += 256) {
            int n  = f >> 4;
            int d4 = (f & 15) << 2;
            const float* kp = qbase + (size_t)(k0 + n) * rowstride + EE + d4;
            float4 kv = *(const float4*)kp;
            Ks[d4 + 0][n] = kv.x;
            Ks[d4 + 1][n] = kv.y;
            Ks[d4 + 2][n] = kv.z;
            Ks[d4 + 3][n] = kv.w;
            const float* vp = qbase + (size_t)(k0 + n) * rowstride + 2 * EE + d4;
            *(float4*)&Vs[n][d4] = *(const float4*)vp;
        }
        __syncthreads();

        float s[4][4] = {};
#pragma unroll 8
        for (int d = 0; d < 64; ++d) {
            float4 a4 = *(const float4*)&Qs[d][tr << 2];
            float4 b4 = *(const float4*)&Ks[d][tc << 2];
            float a[4] = {a4.x, a4.y, a4.z, a4.w};
            float bq[4] = {b4.x, b4.y, b4.z, b4.w};
#pragma unroll
            for (int i = 0; i < 4; ++i)
#pragma unroll
                for (int j = 0; j < 4; ++j)
                    s[i][j] += a[i] * bq[j];
        }

        const bool diag = (kb == nkb - 1);
#pragma unroll
        for (int i = 0; i < 4; ++i) {
            const int qi = (tr << 2) + i;
#pragma unroll
            for (int j = 0; j < 4; ++j) {
                const int kj = (tc << 2) + j;
                float v = s[i][j] * 0.125f;
                s[i][j] = (!diag || (kj <= qi)) ? v : -1e30f;
            }
        }

#pragma unroll
        for (int i = 0; i < 4; ++i) {
            float rmax = fmaxf(fmaxf(s[i][0], s[i][1]), fmaxf(s[i][2], s[i][3]));
#pragma unroll
            for (int off = 1; off < 16; off <<= 1)
                rmax = fmaxf(rmax, __shfl_xor_sync(0xffffffffu, rmax, off, 16));
            const float mn = fmaxf(m_i[i], rmax);
            const float c  = __expf(m_i[i] - mn);
            m_i[i] = mn;

            float rsum = 0.f;
#pragma unroll
            for (int j = 0; j < 4; ++j) {
                s[i][j] = __expf(s[i][j] - mn);
                rsum += s[i][j];
            }
#pragma unroll
            for (int off = 1; off < 16; off <<= 1)
                rsum += __shfl_xor_sync(0xffffffffu, rsum, off, 16);
            l_i[i] = l_i[i] * c + rsum;
#pragma unroll
            for (int j = 0; j < 4; ++j) o[i][j] *= c;
        }

#pragma unroll
        for (int j = 0; j < 64; ++j) {
            const int src = j >> 2;
            const int jj  = j & 3;
            float4 v4 = *(const float4*)&Vs[j][tc << 2];
            float p0 = __shfl_sync(0xffffffffu, s[0][jj], src, 16);
            float p1 = __shfl_sync(0xffffffffu, s[1][jj], src, 16);
            float p2 = __shfl_sync(0xffffffffu, s[2][jj], src, 16);
            float p3 = __shfl_sync(0xffffffffu, s[3][jj], src, 16);
            o[0][0] += p0 * v4.x; o[0][1] += p0 * v4.y; o[0][2] += p0 * v4.z; o[0][3] += p0 * v4.w;
            o[1][0] += p1 * v4.x; o[1][1] += p1 * v4.y; o[1][2] += p1 * v4.z; o[1][3] += p1 * v4.w;
            o[2][0] += p2 * v4.x; o[2][1] += p2 * v4.y; o[2][2] += p2 * v4.z; o[2][3] += p2 * v4.w;
            o[3][0] += p3 * v4.x; o[3][1] += p3 * v4.y; o[3][2] += p3 * v4.z; o[3][3] += p3 * v4.w;
        }
        __syncthreads();
    }

#pragma unroll
    for (int i = 0; i < 4; ++i) {
        const float inv = 1.0f / l_i[i];
        const int row = q0 + (tr << 2) + i;
        float4 ov;
        ov.x = o[i][0] * inv;
        ov.y = o[i][1] * inv;
        ov.z = o[i][2] * inv;
        ov.w = o[i][3] * inv;
        *(float4*)(y + (size_t)(b * TT + row) * EE + h * DD + (tc << 2)) = ov;
    }
}

// ---------------------------------------------------------------------------
// Launch
// ---------------------------------------------------------------------------
extern "C" void kernel_launch(void* const* d_in, const int* in_sizes, int n_in,
                              void* d_out, int out_size)
{
    const float* x     = (const float*)d_in[0];
    const float* Wqkv  = (const float*)d_in[1];
    const float* bqkv  = (const float*)d_in[2];
    const float* Wproj = (const float*)d_in[3];
    const float* bproj = (const float*)d_in[4];
    float* out = (float*)d_out;

    float *qkv, *y, *wqkvT, *wprojT;
    cudaGetSymbolAddress((void**)&qkv, g_qkv);
    cudaGetSymbolAddress((void**)&y, g_y);
    cudaGetSymbolAddress((void**)&wqkvT, g_wqkvT);
    cudaGetSymbolAddress((void**)&wprojT, g_wprojT);

    cudaFuncSetAttribute(gemm_mma_tf32,
                         cudaFuncAttributeMaxDynamicSharedMemorySize, GEMM_SMEM_BYTES);

    const int M = BB * TT;

    // 0) Transpose weights to K-major ([N,K])
    transpose_kernel<<<dim3(3 * EE / 32, EE / 32), dim3(32, 8)>>>(Wqkv, wqkvT, EE, 3 * EE);
    transpose_kernel<<<dim3(EE / 32, EE / 32), dim3(32, 8)>>>(Wproj, wprojT, EE, EE);

    // 1) QKV projection: [M,E] @ [E,3E] + b  (mma.sync tf32)
    gemm_mma_tf32<<<dim3(3 * EE / 128, M / 128), 256, GEMM_SMEM_BYTES>>>(
        x, wqkvT, bqkv, qkv, M, 3 * EE, EE);

    // 2) Causal flash attention
    attn_kernel_v2<<<dim3(TT / 64, HH, BB), 256>>>(qkv, y);

    // 3) Output projection: [M,E] @ [E,E] + b  (mma.sync tf32)
    gemm_mma_tf32<<<dim3(EE / 128, M / 128), 256, GEMM_SMEM_BYTES>>>(
        y, wprojT, bproj, out, M, EE, EE);
}

// round 5
// speedup vs baseline: 3.3361x; 1.9664x over previous
#include <cuda_runtime.h>
#include <math.h>
#include <stdint.h>

// Problem dims (fixed by reference)
#define BB 4
#define TT 2048
#define EE 1024
#define HH 16
#define DD 64

// Scratch (allocation is banned; use __device__ globals)
__device__ float g_qkv[(size_t)BB * TT * 3 * EE];   // [B,T,3E]
__device__ float g_y[(size_t)BB * TT * EE];         // [B,T,E]
__device__ float g_wqkvT[(size_t)3 * EE * EE];      // [3E, E]  (W_qkv^T, K-major)
__device__ float g_wprojT[(size_t)EE * EE];         // [E, E]   (W_proj^T, K-major)

__device__ __forceinline__ uint32_t f2tf32(float f) {
    uint32_t r;
    asm("cvt.rna.tf32.f32 %0, %1;" : "=r"(r) : "f"(f));
    return r;
}

__device__ __forceinline__ void mma_tf32(float c[4], uint32_t a0, uint32_t a1,
                                         uint32_t a2, uint32_t a3,
                                         uint32_t b0, uint32_t b1) {
    asm volatile(
        "mma.sync.aligned.m16n8k8.row.col.f32.tf32.tf32.f32 "
        "{%0,%1,%2,%3}, {%4,%5,%6,%7}, {%8,%9}, {%0,%1,%2,%3};"
        : "+f"(c[0]), "+f"(c[1]), "+f"(c[2]), "+f"(c[3])
        : "r"(a0), "r"(a1), "r"(a2), "r"(a3), "r"(b0), "r"(b1));
}

// ---------------------------------------------------------------------------
// Transpose: out[c][r] = in[r][c], R x C, both multiples of 32
// ---------------------------------------------------------------------------
__global__ __launch_bounds__(256) void transpose_kernel(
    const float* __restrict__ in, float* __restrict__ out, int R, int C)
{
    __shared__ float t[32][33];
    int x = blockIdx.x * 32 + threadIdx.x;
    int y = blockIdx.y * 32 + threadIdx.y;
#pragma unroll
    for (int j = 0; j < 32; j += 8)
        t[threadIdx.y + j][threadIdx.x] = in[(size_t)(y + j) * C + x];
    __syncthreads();
    x = blockIdx.y * 32 + threadIdx.x;
    y = blockIdx.x * 32 + threadIdx.y;
#pragma unroll
    for (int j = 0; j < 32; j += 8)
        out[(size_t)(y + j) * R + x] = t[threadIdx.x][threadIdx.y + j];
}

// ---------------------------------------------------------------------------
// mma.sync tf32 GEMM: C[M,N] = A[M,K] @ Bt[N,K]^T + bias[N]
// (unchanged from round 4)
// ---------------------------------------------------------------------------
#define SMS 36
#define TILE_F (128 * SMS)
#define GEMM_SMEM_BYTES (2 * 2 * TILE_F * 4)

__global__ __launch_bounds__(256) void gemm_mma_tf32(
    const float* __restrict__ A, const float* __restrict__ Bt,
    const float* __restrict__ bias, float* __restrict__ C,
    int M, int N, int K)
{
    extern __shared__ float smem[];
    float* As = smem;               // [2][128][SMS]
    float* Bs = smem + 2 * TILE_F;  // [2][128][SMS]

    const int tid  = threadIdx.x;
    const int wid  = tid >> 5;
    const int lane = tid & 31;
    const int wm   = wid >> 2;
    const int wn   = wid & 3;
    const int r1   = lane >> 2;
    const int cg   = lane & 3;
    const int m0   = blockIdx.y << 7;
    const int n0   = blockIdx.x << 7;

    const float* Ap  = A  + (size_t)m0 * K;
    const float* Btp = Bt + (size_t)n0 * K;

    const int lr  = tid >> 3;
    const int lc4 = (tid & 7) << 2;

#pragma unroll
    for (int i = 0; i < 4; ++i) {
        const int r = lr + (i << 5);
        float4 va = *(const float4*)(Ap  + (size_t)r * K + lc4);
        float4 vb = *(const float4*)(Btp + (size_t)r * K + lc4);
        uint4 ua = make_uint4(f2tf32(va.x), f2tf32(va.y), f2tf32(va.z), f2tf32(va.w));
        uint4 ub = make_uint4(f2tf32(vb.x), f2tf32(vb.y), f2tf32(vb.z), f2tf32(vb.w));
        *(uint4*)(As + r * SMS + lc4) = ua;
        *(uint4*)(Bs + r * SMS + lc4) = ub;
    }
    __syncthreads();

    float acc[4][4][4] = {};
    float4 aR[4], bR[4];

    const int nT = K >> 5;
    for (int t = 0; t < nT; ++t) {
        const int buf = t & 1;
        const bool more = (t + 1 < nT);
        if (more) {
            const int k0 = (t + 1) << 5;
#pragma unroll
            for (int i = 0; i < 4; ++i) {
                const int r = lr + (i << 5);
                aR[i] = *(const float4*)(Ap  + (size_t)r * K + k0 + lc4);
                bR[i] = *(const float4*)(Btp + (size_t)r * K + k0 + lc4);
            }
        }

        const float* Ab = As + buf * TILE_F;
        const float* Bb = Bs + buf * TILE_F;
#pragma unroll
        for (int ks = 0; ks < 4; ++ks) {
            const int kk = ks << 3;
            uint32_t bf[4][2];
#pragma unroll
            for (int nt = 0; nt < 4; ++nt) {
                const float* p = Bb + (wn * 32 + nt * 8 + r1) * SMS + kk + cg;
                bf[nt][0] = __float_as_uint(p[0]);
                bf[nt][1] = __float_as_uint(p[4]);
            }
#pragma unroll
            for (int mt = 0; mt < 4; ++mt) {
                const float* p = Ab + (wm * 64 + mt * 16 + r1) * SMS + kk + cg;
                uint32_t a0 = __float_as_uint(p[0]);
                uint32_t a1 = __float_as_uint(p[8 * SMS]);
                uint32_t a2 = __float_as_uint(p[4]);
                uint32_t a3 = __float_as_uint(p[8 * SMS + 4]);
#pragma unroll
                for (int nt = 0; nt < 4; ++nt)
                    mma_tf32(acc[mt][nt], a0, a1, a2, a3, bf[nt][0], bf[nt][1]);
            }
        }

        if (more) {
            const int nxt = (t + 1) & 1;
            __syncthreads();
#pragma unroll
            for (int i = 0; i < 4; ++i) {
                const int r = lr + (i << 5);
                uint4 ua = make_uint4(f2tf32(aR[i].x), f2tf32(aR[i].y),
                                      f2tf32(aR[i].z), f2tf32(aR[i].w));
                uint4 ub = make_uint4(f2tf32(bR[i].x), f2tf32(bR[i].y),
                                      f2tf32(bR[i].z), f2tf32(bR[i].w));
                *(uint4*)(As + nxt * TILE_F + r * SMS + lc4) = ua;
                *(uint4*)(Bs + nxt * TILE_F + r * SMS + lc4) = ub;
            }
            __syncthreads();
        }
    }

#pragma unroll
    for (int mt = 0; mt < 4; ++mt) {
#pragma unroll
        for (int nt = 0; nt < 4; ++nt) {
            const int row = m0 + wm * 64 + mt * 16 + r1;
            const int col = n0 + wn * 32 + nt * 8 + 2 * cg;
            const float2 bv = *(const float2*)(bias + col);
            float2 o0, o1;
            o0.x = acc[mt][nt][0] + bv.x;
            o0.y = acc[mt][nt][1] + bv.y;
            o1.x = acc[mt][nt][2] + bv.x;
            o1.y = acc[mt][nt][3] + bv.y;
            *(float2*)(C + (size_t)row * N + col) = o0;
            *(float2*)(C + (size_t)(row + 8) * N + col) = o1;
        }
    }
}

// ---------------------------------------------------------------------------
// Tensor-core flash attention (causal), mma.sync m16n8k8 tf32.
// CTA: 128 queries, 8 warps (warp = 16 query rows). Key tiles of 64.
// Q pre-scaled by 1/8, held as A-frags in registers. K,V in smem stride 68.
// S/softmax in C-frag registers; P via per-warp smem strip (syncwarp only).
// ---------------------------------------------------------------------------
#define AST 68                           // smem row stride (floats)
#define ATT_SMEM_FLOATS (128 * AST + 8 * 16 * AST)
#define ATT_SMEM_BYTES (ATT_SMEM_FLOATS * 4)

__global__ __launch_bounds__(256, 2) void attn_mma(
    const float* __restrict__ qkv, float* __restrict__ y)
{
    extern __shared__ float sm[];
    float* Ks = sm;                  // [64][AST]
    float* Vs = sm + 64 * AST;       // [64][AST]
    float* Pw = sm + 128 * AST;      // [8][16][AST]

    const int tid  = threadIdx.x;
    const int wid  = tid >> 5;
    const int lane = tid & 31;
    const int r1   = lane >> 2;      // 0..7
    const int cg   = lane & 3;       // 0..3
    const int q0   = blockIdx.x << 7;
    const int h    = blockIdx.y;
    const int b    = blockIdx.z;
    const int qw   = q0 + (wid << 4);   // warp's first query row

    const size_t rs = (size_t)3 * EE;
    const float* base = qkv + (size_t)(b * TT) * rs + h * DD;

    // ---- Stage Q (scaled + tf32) into sm[0 .. 128*AST) ----
#pragma unroll
    for (int i = 0; i < 8; ++i) {
        const int idx = tid + (i << 8);
        const int row = idx >> 4;
        const int d4  = (idx & 15) << 2;
        float4 v = *(const float4*)(base + (size_t)(q0 + row) * rs + d4);
        uint4 u = make_uint4(f2tf32(v.x * 0.125f), f2tf32(v.y * 0.125f),
                             f2tf32(v.z * 0.125f), f2tf32(v.w * 0.125f));
        *(uint4*)(sm + row * AST + d4) = u;
    }
    __syncthreads();

    // ---- Q A-fragments: 8 k-steps x 4 regs ----
    uint32_t qf[8][4];
#pragma unroll
    for (int ks = 0; ks < 8; ++ks) {
        const float* p = sm + ((wid << 4) + r1) * AST + (ks << 3) + cg;
        qf[ks][0] = __float_as_uint(p[0]);
        qf[ks][1] = __float_as_uint(p[8 * AST]);
        qf[ks][2] = __float_as_uint(p[4]);
        qf[ks][3] = __float_as_uint(p[8 * AST + 4]);
    }
    __syncthreads();

    float o[8][4] = {};
    float m0r = -INFINITY, m1r = -INFINITY;
    float l0r = 0.f, l1r = 0.f;

    const int nkb = (q0 >> 6) + 2;

    for (int kb = 0; kb < nkb; ++kb) {
        const int k0 = kb << 6;

        // ---- Load K,V tiles (tf32-converted) ----
#pragma unroll
        for (int i = 0; i < 4; ++i) {
            const int idx = tid + (i << 8);
            const int row = idx >> 4;
            const int d4  = (idx & 15) << 2;
            const float* kp = base + (size_t)(k0 + row) * rs + EE + d4;
            const float* vp = base + (size_t)(k0 + row) * rs + 2 * EE + d4;
            float4 kv = *(const float4*)kp;
            float4 vv = *(const float4*)vp;
            *(uint4*)(Ks + row * AST + d4) =
                make_uint4(f2tf32(kv.x), f2tf32(kv.y), f2tf32(kv.z), f2tf32(kv.w));
            *(uint4*)(Vs + row * AST + d4) =
                make_uint4(f2tf32(vv.x), f2tf32(vv.y), f2tf32(vv.z), f2tf32(vv.w));
        }
        __syncthreads();

        if (k0 <= qw + 15) {       // warp has at least one unmasked element
            // ---- S = Qs @ K^T : 8 n-frags ----
            float s[8][4] = {};
#pragma unroll
            for (int ks = 0; ks < 8; ++ks) {
#pragma unroll
                for (int nt = 0; nt < 8; ++nt) {
                    const float* p = Ks + ((nt << 3) + r1) * AST + (ks << 3) + cg;
                    mma_tf32(s[nt], qf[ks][0], qf[ks][1], qf[ks][2], qf[ks][3],
                             __float_as_uint(p[0]), __float_as_uint(p[4]));
                }
            }

            // ---- Causal mask (only partially-masked tiles) ----
            if (k0 + 63 > qw) {
                const int row0 = qw + r1, row1 = row0 + 8;
#pragma unroll
                for (int nt = 0; nt < 8; ++nt) {
                    const int col = k0 + (nt << 3) + 2 * cg;
                    if (col > row0)     s[nt][0] = -1e30f;
                    if (col + 1 > row0) s[nt][1] = -1e30f;
                    if (col > row1)     s[nt][2] = -1e30f;
                    if (col + 1 > row1) s[nt][3] = -1e30f;
                }
            }

            // ---- Online softmax (row halves r1 and r1+8) ----
            float mx0 = -INFINITY, mx1 = -INFINITY;
#pragma unroll
            for (int nt = 0; nt < 8; ++nt) {
                mx0 = fmaxf(mx0, fmaxf(s[nt][0], s[nt][1]));
                mx1 = fmaxf(mx1, fmaxf(s[nt][2], s[nt][3]));
            }
            mx0 = fmaxf(mx0, __shfl_xor_sync(0xffffffffu, mx0, 1));
            mx0 = fmaxf(mx0, __shfl_xor_sync(0xffffffffu, mx0, 2));
            mx1 = fmaxf(mx1, __shfl_xor_sync(0xffffffffu, mx1, 1));
            mx1 = fmaxf(mx1, __shfl_xor_sync(0xffffffffu, mx1, 2));

            const float mn0 = fmaxf(m0r, mx0);
            const float mn1 = fmaxf(m1r, mx1);
            const float c0 = __expf(m0r - mn0);
            const float c1 = __expf(m1r - mn1);
            m0r = mn0; m1r = mn1;

            float sum0 = 0.f, sum1 = 0.f;
#pragma unroll
            for (int nt = 0; nt < 8; ++nt) {
                s[nt][0] = __expf(s[nt][0] - mn0);
                s[nt][1] = __expf(s[nt][1] - mn0);
                s[nt][2] = __expf(s[nt][2] - mn1);
                s[nt][3] = __expf(s[nt][3] - mn1);
                sum0 += s[nt][0] + s[nt][1];
                sum1 += s[nt][2] + s[nt][3];
            }
            sum0 += __shfl_xor_sync(0xffffffffu, sum0, 1);
            sum0 += __shfl_xor_sync(0xffffffffu, sum0, 2);
            sum1 += __shfl_xor_sync(0xffffffffu, sum1, 1);
            sum1 += __shfl_xor_sync(0xffffffffu, sum1, 2);
            l0r = l0r * c0 + sum0;
            l1r = l1r * c1 + sum1;

#pragma unroll
            for (int nt = 0; nt < 8; ++nt) {
                o[nt][0] *= c0; o[nt][1] *= c0;
                o[nt][2] *= c1; o[nt][3] *= c1;
            }

            // ---- P -> per-warp smem strip (tf32 bits) ----
            float* pw = Pw + wid * 16 * AST;
#pragma unroll
            for (int nt = 0; nt < 8; ++nt) {
                float2 p01, p23;
                p01.x = __uint_as_float(f2tf32(s[nt][0]));
                p01.y = __uint_as_float(f2tf32(s[nt][1]));
                p23.x = __uint_as_float(f2tf32(s[nt][2]));
                p23.y = __uint_as_float(f2tf32(s[nt][3]));
                *(float2*)(pw + r1 * AST + (nt << 3) + 2 * cg) = p01;
                *(float2*)(pw + (r1 + 8) * AST + (nt << 3) + 2 * cg) = p23;
            }
            __syncwarp();

            // ---- O += P @ V ----
#pragma unroll
            for (int ks = 0; ks < 8; ++ks) {
                const float* pa = pw + r1 * AST + (ks << 3) + cg;
                const uint32_t a0 = __float_as_uint(pa[0]);
                const uint32_t a1 = __float_as_uint(pa[8 * AST]);
                const uint32_t a2 = __float_as_uint(pa[4]);
                const uint32_t a3 = __float_as_uint(pa[8 * AST + 4]);
#pragma unroll
                for (int nt = 0; nt < 8; ++nt) {
                    const float* pv = Vs + ((ks << 3) + cg) * AST + (nt << 3) + r1;
                    mma_tf32(o[nt], a0, a1, a2, a3,
                             __float_as_uint(pv[0]), __float_as_uint(pv[4 * AST]));
                }
            }
            __syncwarp();
        }
        __syncthreads();
    }

    // ---- Normalize + write ----
    const float inv0 = 1.0f / l0r;
    const float inv1 = 1.0f / l1r;
    const size_t row0 = (size_t)(b * TT + qw + r1);
#pragma unroll
    for (int nt = 0; nt < 8; ++nt) {
        const int col = h * DD + (nt << 3) + 2 * cg;
        float2 o0, o1;
        o0.x = o[nt][0] * inv0; o0.y = o[nt][1] * inv0;
        o1.x = o[nt][2] * inv1; o1.y = o[nt][3] * inv1;
        *(float2*)(y + row0 * EE + col) = o0;
        *(float2*)(y + (row0 + 8) * EE + col) = o1;
    }
}

// ---------------------------------------------------------------------------
// Launch
// ---------------------------------------------------------------------------
extern "C" void kernel_launch(void* const* d_in, const int* in_sizes, int n_in,
                              void* d_out, int out_size)
{
    const float* x     = (const float*)d_in[0];
    const float* Wqkv  = (const float*)d_in[1];
    const float* bqkv  = (const float*)d_in[2];
    const float* Wproj = (const float*)d_in[3];
    const float* bproj = (const float*)d_in[4];
    float* out = (float*)d_out;

    float *qkv, *y, *wqkvT, *wprojT;
    cudaGetSymbolAddress((void**)&qkv, g_qkv);
    cudaGetSymbolAddress((void**)&y, g_y);
    cudaGetSymbolAddress((void**)&wqkvT, g_wqkvT);
    cudaGetSymbolAddress((void**)&wprojT, g_wprojT);

    cudaFuncSetAttribute(gemm_mma_tf32,
                         cudaFuncAttributeMaxDynamicSharedMemorySize, GEMM_SMEM_BYTES);
    cudaFuncSetAttribute(attn_mma,
                         cudaFuncAttributeMaxDynamicSharedMemorySize, ATT_SMEM_BYTES);

    const int M = BB * TT;

    // 0) Transpose weights to K-major ([N,K])
    transpose_kernel<<<dim3(3 * EE / 32, EE / 32), dim3(32, 8)>>>(Wqkv, wqkvT, EE, 3 * EE);
    transpose_kernel<<<dim3(EE / 32, EE / 32), dim3(32, 8)>>>(Wproj, wprojT, EE, EE);

    // 1) QKV projection (mma.sync tf32)
    gemm_mma_tf32<<<dim3(3 * EE / 128, M / 128), 256, GEMM_SMEM_BYTES>>>(
        x, wqkvT, bqkv, qkv, M, 3 * EE, EE);

    // 2) Causal flash attention (mma.sync tf32)
    attn_mma<<<dim3(TT / 128, HH, BB), 256, ATT_SMEM_BYTES>>>(qkv, y);

    // 3) Output projection (mma.sync tf32)
    gemm_mma_tf32<<<dim3(EE / 128, M / 128), 256, GEMM_SMEM_BYTES>>>(
        y, wprojT, bproj, out, M, EE, EE);
}

// round 6
// speedup vs baseline: 3.5287x; 1.0577x over previous
#include <cuda_runtime.h>
#include <math.h>
#include <stdint.h>

// Problem dims (fixed by reference)
#define BB 4
#define TT 2048
#define EE 1024
#define HH 16
#define DD 64

// Scratch (allocation is banned; use __device__ globals)
__device__ float g_qkv[(size_t)BB * TT * 3 * EE];   // [B,T,3E] tf32 bits, Q pre-scaled
__device__ float g_y[(size_t)BB * TT * EE];         // [B,T,E]  tf32 bits
__device__ float g_xt[(size_t)BB * TT * EE];        // x as tf32 bits
__device__ float g_wqkvT[(size_t)3 * EE * EE];      // W_qkv^T, K-major, tf32 bits
__device__ float g_wprojT[(size_t)EE * EE];         // W_proj^T, K-major, tf32 bits

__device__ __forceinline__ uint32_t f2tf32(float f) {
    uint32_t r;
    asm("cvt.rna.tf32.f32 %0, %1;" : "=r"(r) : "f"(f));
    return r;
}

__device__ __forceinline__ void mma_tf32(float c[4], uint32_t a0, uint32_t a1,
                                         uint32_t a2, uint32_t a3,
                                         uint32_t b0, uint32_t b1) {
    asm volatile(
        "mma.sync.aligned.m16n8k8.row.col.f32.tf32.tf32.f32 "
        "{%0,%1,%2,%3}, {%4,%5,%6,%7}, {%8,%9}, {%0,%1,%2,%3};"
        : "+f"(c[0]), "+f"(c[1]), "+f"(c[2]), "+f"(c[3])
        : "r"(a0), "r"(a1), "r"(a2), "r"(a3), "r"(b0), "r"(b1));
}

__device__ __forceinline__ void cp16(float* dst_smem, const float* src) {
    uint32_t d = (uint32_t)__cvta_generic_to_shared(dst_smem);
    asm volatile("cp.async.cg.shared.global [%0], [%1], 16;"
                 :: "r"(d), "l"(src) : "memory");
}
#define CP_COMMIT() asm volatile("cp.async.commit_group;" ::: "memory")
#define CP_WAIT1()  asm volatile("cp.async.wait_group 1;" ::: "memory")

// ---------------------------------------------------------------------------
// x -> tf32 bits (elementwise)
// ---------------------------------------------------------------------------
__global__ __launch_bounds__(256) void cvt_tf32_kernel(
    const float* __restrict__ in, float* __restrict__ out)
{
    const size_t i = ((size_t)blockIdx.x * 256 + threadIdx.x) * 4;
    float4 v = *(const float4*)(in + i);
    uint4 u = make_uint4(f2tf32(v.x), f2tf32(v.y), f2tf32(v.z), f2tf32(v.w));
    *(uint4*)(out + i) = u;
}

// ---------------------------------------------------------------------------
// Transpose + tf32 convert: out[c][r] = tf32(in[r][c])
// ---------------------------------------------------------------------------
__global__ __launch_bounds__(256) void transpose_kernel(
    const float* __restrict__ in, float* __restrict__ out, int R, int C)
{
    __shared__ float t[32][33];
    int x = blockIdx.x * 32 + threadIdx.x;
    int y = blockIdx.y * 32 + threadIdx.y;
#pragma unroll
    for (int j = 0; j < 32; j += 8)
        t[threadIdx.y + j][threadIdx.x] = in[(size_t)(y + j) * C + x];
    __syncthreads();
    x = blockIdx.y * 32 + threadIdx.x;
    y = blockIdx.x * 32 + threadIdx.y;
#pragma unroll
    for (int j = 0; j < 32; j += 8)
        out[(size_t)(y + j) * R + x] =
            __uint_as_float(f2tf32(t[threadIdx.x][threadIdx.y + j]));
}

// ---------------------------------------------------------------------------
// mma.sync tf32 GEMM with cp.async double-buffering.
// Inputs A, Bt already hold tf32 bits. C[M,N] = A@Bt^T + bias.
// MODE 0: plain fp32 output. MODE 1: tf32-convert output, scale cols<EE by 1/8.
// ---------------------------------------------------------------------------
#define SMS 36
#define TILE_F (128 * SMS)
#define GEMM_SMEM_BYTES (2 * 2 * TILE_F * 4)

template <int MODE>
__global__ __launch_bounds__(256) void gemm_mma_tf32(
    const float* __restrict__ A, const float* __restrict__ Bt,
    const float* __restrict__ bias, float* __restrict__ C,
    int M, int N, int K)
{
    extern __shared__ float smem[];
    float* As = smem;               // [2][128][SMS]
    float* Bs = smem + 2 * TILE_F;  // [2][128][SMS]

    const int tid  = threadIdx.x;
    const int wid  = tid >> 5;
    const int lane = tid & 31;
    const int wm   = wid >> 2;
    const int wn   = wid & 3;
    const int r1   = lane >> 2;
    const int cg   = lane & 3;
    const int m0   = blockIdx.y << 7;
    const int n0   = blockIdx.x << 7;

    const float* Ap  = A  + (size_t)m0 * K;
    const float* Btp = Bt + (size_t)n0 * K;

    const int lr  = tid >> 3;          // base row, +32 per iter
    const int lc4 = (tid & 7) << 2;    // float col 0..28

    // Prologue: tile 0 -> buffer 0
#pragma unroll
    for (int i = 0; i < 4; ++i) {
        const int r = lr + (i << 5);
        cp16(As + r * SMS + lc4, Ap + (size_t)r * K + lc4);
        cp16(Bs + r * SMS + lc4, Btp + (size_t)r * K + lc4);
    }
    CP_COMMIT();

    float acc[4][4][4] = {};

    const int nT = K >> 5;
    for (int t = 0; t < nT; ++t) {
        const int buf = t & 1;
        if (t + 1 < nT) {
            const int k0 = (t + 1) << 5;
            const int nxt = (t + 1) & 1;
#pragma unroll
            for (int i = 0; i < 4; ++i) {
                const int r = lr + (i << 5);
                cp16(As + nxt * TILE_F + r * SMS + lc4, Ap + (size_t)r * K + k0 + lc4);
                cp16(Bs + nxt * TILE_F + r * SMS + lc4, Btp + (size_t)r * K + k0 + lc4);
            }
        }
        CP_COMMIT();
        CP_WAIT1();
        __syncthreads();

        const float* Ab = As + buf * TILE_F;
        const float* Bb = Bs + buf * TILE_F;
#pragma unroll
        for (int ks = 0; ks < 4; ++ks) {
            const int kk = ks << 3;
            uint32_t bf[4][2];
#pragma unroll
            for (int nt = 0; nt < 4; ++nt) {
                const float* p = Bb + (wn * 32 + nt * 8 + r1) * SMS + kk + cg;
                bf[nt][0] = __float_as_uint(p[0]);
                bf[nt][1] = __float_as_uint(p[4]);
            }
#pragma unroll
            for (int mt = 0; mt < 4; ++mt) {
                const float* p = Ab + (wm * 64 + mt * 16 + r1) * SMS + kk + cg;
                uint32_t a0 = __float_as_uint(p[0]);
                uint32_t a1 = __float_as_uint(p[8 * SMS]);
                uint32_t a2 = __float_as_uint(p[4]);
                uint32_t a3 = __float_as_uint(p[8 * SMS + 4]);
#pragma unroll
                for (int nt = 0; nt < 4; ++nt)
                    mma_tf32(acc[mt][nt], a0, a1, a2, a3, bf[nt][0], bf[nt][1]);
            }
        }
        __syncthreads();
    }

    // Epilogue
#pragma unroll
    for (int mt = 0; mt < 4; ++mt) {
#pragma unroll
        for (int nt = 0; nt < 4; ++nt) {
            const int row = m0 + wm * 64 + mt * 16 + r1;
            const int col = n0 + wn * 32 + nt * 8 + 2 * cg;
            const float2 bv = *(const float2*)(bias + col);
            float v[4];
            v[0] = acc[mt][nt][0] + bv.x;
            v[1] = acc[mt][nt][1] + bv.y;
            v[2] = acc[mt][nt][2] + bv.x;
            v[3] = acc[mt][nt][3] + bv.y;
            if (MODE == 1) {
                const float sc = (col < EE) ? 0.125f : 1.0f; // Q cols pre-scaled
#pragma unroll
                for (int q = 0; q < 4; ++q)
                    v[q] = __uint_as_float(f2tf32(v[q] * sc));
            }
            *(float2*)(C + (size_t)row * N + col) = make_float2(v[0], v[1]);
            *(float2*)(C + (size_t)(row + 8) * N + col) = make_float2(v[2], v[3]);
        }
    }
}

// ---------------------------------------------------------------------------
// Tensor-core flash attention (causal), mma.sync tf32 + cp.async double buffer.
// qkv holds tf32 bits with Q pre-scaled. CTA: 128 queries, 8 warps.
// Key tiles of 64; K rows 0-63 and V rows 64-127 of each buffer.
// ---------------------------------------------------------------------------
#define AST 68                           // smem row stride (floats)
#define ATT_SMEM_FLOATS (2 * 128 * AST + 8 * 16 * AST)
#define ATT_SMEM_BYTES (ATT_SMEM_FLOATS * 4)

__global__ __launch_bounds__(256, 2) void attn_mma(
    const float* __restrict__ qkv, float* __restrict__ y)
{
    extern __shared__ float sm[];
    float* Pw = sm + 2 * 128 * AST;      // [8][16][AST]

    const int tid  = threadIdx.x;
    const int wid  = tid >> 5;
    const int lane = tid & 31;
    const int r1   = lane >> 2;
    const int cg   = lane & 3;
    const int q0   = blockIdx.x << 7;
    const int h    = blockIdx.y;
    const int b    = blockIdx.z;
    const int qw   = q0 + (wid << 4);

    const size_t rs = (size_t)3 * EE;
    const float* base = qkv + (size_t)(b * TT) * rs + h * DD;

    // ---- Stage Q (already scaled tf32 bits) into sm[0 .. 128*AST) ----
#pragma unroll
    for (int i = 0; i < 8; ++i) {
        const int idx = tid + (i << 8);
        const int row = idx >> 4;
        const int d4  = (idx & 15) << 2;
        *(float4*)(sm + row * AST + d4) =
            *(const float4*)(base + (size_t)(q0 + row) * rs + d4);
    }
    __syncthreads();

    uint32_t qf[8][4];
#pragma unroll
    for (int ks = 0; ks < 8; ++ks) {
        const float* p = sm + ((wid << 4) + r1) * AST + (ks << 3) + cg;
        qf[ks][0] = __float_as_uint(p[0]);
        qf[ks][1] = __float_as_uint(p[8 * AST]);
        qf[ks][2] = __float_as_uint(p[4]);
        qf[ks][3] = __float_as_uint(p[8 * AST + 4]);
    }
    __syncthreads();

    const int nkb = (q0 >> 6) + 2;

    // staging indices: 256 threads x 4 iters cover 64 rows x 16 float4
    const int srow = tid >> 4;          // 0..15, +16 per iter
    const int sd4  = (tid & 15) << 2;   // 0..60

    // Prologue: tile 0 -> buffer 0
#pragma unroll
    for (int i = 0; i < 4; ++i) {
        const int row = srow + (i << 4);
        const float* kp = base + (size_t)row * rs + EE + sd4;
        const float* vp = base + (size_t)row * rs + 2 * EE + sd4;
        cp16(sm + row * AST + sd4, kp);
        cp16(sm + (64 + row) * AST + sd4, vp);
    }
    CP_COMMIT();

    float o[8][4] = {};
    float m0r = -INFINITY, m1r = -INFINITY;
    float l0r = 0.f, l1r = 0.f;

    for (int kb = 0; kb < nkb; ++kb) {
        const int buf = kb & 1;
        if (kb + 1 < nkb) {
            const int k0n = (kb + 1) << 6;
            float* nb = sm + ((kb + 1) & 1) * 128 * AST;
#pragma unroll
            for (int i = 0; i < 4; ++i) {
                const int row = srow + (i << 4);
                const float* kp = base + (size_t)(k0n + row) * rs + EE + sd4;
                const float* vp = base + (size_t)(k0n + row) * rs + 2 * EE + sd4;
                cp16(nb + row * AST + sd4, kp);
                cp16(nb + (64 + row) * AST + sd4, vp);
            }
        }
        CP_COMMIT();
        CP_WAIT1();
        __syncthreads();

        const int k0 = kb << 6;
        const float* Ks = sm + buf * 128 * AST;
        const float* Vs = Ks + 64 * AST;

        if (k0 <= qw + 15) {
            // ---- S = Qs @ K^T ----
            float s[8][4] = {};
#pragma unroll
            for (int ks = 0; ks < 8; ++ks) {
#pragma unroll
                for (int nt = 0; nt < 8; ++nt) {
                    const float* p = Ks + ((nt << 3) + r1) * AST + (ks << 3) + cg;
                    mma_tf32(s[nt], qf[ks][0], qf[ks][1], qf[ks][2], qf[ks][3],
                             __float_as_uint(p[0]), __float_as_uint(p[4]));
                }
            }

            // ---- Causal mask ----
            if (k0 + 63 > qw) {
                const int row0 = qw + r1, row1 = row0 + 8;
#pragma unroll
                for (int nt = 0; nt < 8; ++nt) {
                    const int col = k0 + (nt << 3) + 2 * cg;
                    if (col > row0)     s[nt][0] = -1e30f;
                    if (col + 1 > row0) s[nt][1] = -1e30f;
                    if (col > row1)     s[nt][2] = -1e30f;
                    if (col + 1 > row1) s[nt][3] = -1e30f;
                }
            }

            // ---- Online softmax ----
            float mx0 = -INFINITY, mx1 = -INFINITY;
#pragma unroll
            for (int nt = 0; nt < 8; ++nt) {
                mx0 = fmaxf(mx0, fmaxf(s[nt][0], s[nt][1]));
                mx1 = fmaxf(mx1, fmaxf(s[nt][2], s[nt][3]));
            }
            mx0 = fmaxf(mx0, __shfl_xor_sync(0xffffffffu, mx0, 1));
            mx0 = fmaxf(mx0, __shfl_xor_sync(0xffffffffu, mx0, 2));
            mx1 = fmaxf(mx1, __shfl_xor_sync(0xffffffffu, mx1, 1));
            mx1 = fmaxf(mx1, __shfl_xor_sync(0xffffffffu, mx1, 2));

            const float mn0 = fmaxf(m0r, mx0);
            const float mn1 = fmaxf(m1r, mx1);
            const float c0 = __expf(m0r - mn0);
            const float c1 = __expf(m1r - mn1);
            m0r = mn0; m1r = mn1;

            float sum0 = 0.f, sum1 = 0.f;
#pragma unroll
            for (int nt = 0; nt < 8; ++nt) {
                s[nt][0] = __expf(s[nt][0] - mn0);
                s[nt][1] = __expf(s[nt][1] - mn0);
                s[nt][2] = __expf(s[nt][2] - mn1);
                s[nt][3] = __expf(s[nt][3] - mn1);
                sum0 += s[nt][0] + s[nt][1];
                sum1 += s[nt][2] + s[nt][3];
            }
            sum0 += __shfl_xor_sync(0xffffffffu, sum0, 1);
            sum0 += __shfl_xor_sync(0xffffffffu, sum0, 2);
            sum1 += __shfl_xor_sync(0xffffffffu, sum1, 1);
            sum1 += __shfl_xor_sync(0xffffffffu, sum1, 2);
            l0r = l0r * c0 + sum0;
            l1r = l1r * c1 + sum1;

#pragma unroll
            for (int nt = 0; nt < 8; ++nt) {
                o[nt][0] *= c0; o[nt][1] *= c0;
                o[nt][2] *= c1; o[nt][3] *= c1;
            }

            // ---- P -> per-warp smem strip (tf32 bits) ----
            float* pw = Pw + wid * 16 * AST;
#pragma unroll
            for (int nt = 0; nt < 8; ++nt) {
                float2 p01, p23;
                p01.x = __uint_as_float(f2tf32(s[nt][0]));
                p01.y = __uint_as_float(f2tf32(s[nt][1]));
                p23.x = __uint_as_float(f2tf32(s[nt][2]));
                p23.y = __uint_as_float(f2tf32(s[nt][3]));
                *(float2*)(pw + r1 * AST + (nt << 3) + 2 * cg) = p01;
                *(float2*)(pw + (r1 + 8) * AST + (nt << 3) + 2 * cg) = p23;
            }
            __syncwarp();

            // ---- O += P @ V ----
#pragma unroll
            for (int ks = 0; ks < 8; ++ks) {
                const float* pa = pw + r1 * AST + (ks << 3) + cg;
                const uint32_t a0 = __float_as_uint(pa[0]);
                const uint32_t a1 = __float_as_uint(pa[8 * AST]);
                const uint32_t a2 = __float_as_uint(pa[4]);
                const uint32_t a3 = __float_as_uint(pa[8 * AST + 4]);
#pragma unroll
                for (int nt = 0; nt < 8; ++nt) {
                    const float* pv = Vs + ((ks << 3) + cg) * AST + (nt << 3) + r1;
                    mma_tf32(o[nt], a0, a1, a2, a3,
                             __float_as_uint(pv[0]), __float_as_uint(pv[4 * AST]));
                }
            }
            __syncwarp();
        }
        __syncthreads();
    }

    // ---- Normalize + write (tf32 bits; y feeds proj GEMM only) ----
    const float inv0 = 1.0f / l0r;
    const float inv1 = 1.0f / l1r;
    const size_t row0 = (size_t)(b * TT + qw + r1);
#pragma unroll
    for (int nt = 0; nt < 8; ++nt) {
        const int col = h * DD + (nt << 3) + 2 * cg;
        float2 o0, o1;
        o0.x = __uint_as_float(f2tf32(o[nt][0] * inv0));
        o0.y = __uint_as_float(f2tf32(o[nt][1] * inv0));
        o1.x = __uint_as_float(f2tf32(o[nt][2] * inv1));
        o1.y = __uint_as_float(f2tf32(o[nt][3] * inv1));
        *(float2*)(y + row0 * EE + col) = o0;
        *(float2*)(y + (row0 + 8) * EE + col) = o1;
    }
}

// ---------------------------------------------------------------------------
// Launch
// ---------------------------------------------------------------------------
extern "C" void kernel_launch(void* const* d_in, const int* in_sizes, int n_in,
                              void* d_out, int out_size)
{
    const float* x     = (const float*)d_in[0];
    const float* Wqkv  = (const float*)d_in[1];
    const float* bqkv  = (const float*)d_in[2];
    const float* Wproj = (const float*)d_in[3];
    const float* bproj = (const float*)d_in[4];
    float* out = (float*)d_out;

    float *qkv, *y, *xt, *wqkvT, *wprojT;
    cudaGetSymbolAddress((void**)&qkv, g_qkv);
    cudaGetSymbolAddress((void**)&y, g_y);
    cudaGetSymbolAddress((void**)&xt, g_xt);
    cudaGetSymbolAddress((void**)&wqkvT, g_wqkvT);
    cudaGetSymbolAddress((void**)&wprojT, g_wprojT);

    cudaFuncSetAttribute(gemm_mma_tf32<0>,
                         cudaFuncAttributeMaxDynamicSharedMemorySize, GEMM_SMEM_BYTES);
    cudaFuncSetAttribute(gemm_mma_tf32<1>,
                         cudaFuncAttributeMaxDynamicSharedMemorySize, GEMM_SMEM_BYTES);
    cudaFuncSetAttribute(attn_mma,
                         cudaFuncAttributeMaxDynamicSharedMemorySize, ATT_SMEM_BYTES);

    const int M = BB * TT;

    // 0) Pre-convert inputs: x -> tf32, W^T -> tf32 K-major
    cvt_tf32_kernel<<<(M * EE) / (256 * 4), 256>>>(x, xt);
    transpose_kernel<<<dim3(3 * EE / 32, EE / 32), dim3(32, 8)>>>(Wqkv, wqkvT, EE, 3 * EE);
    transpose_kernel<<<dim3(EE / 32, EE / 32), dim3(32, 8)>>>(Wproj, wprojT, EE, EE);

    // 1) QKV projection -> tf32 qkv with Q pre-scaled
    gemm_mma_tf32<1><<<dim3(3 * EE / 128, M / 128), 256, GEMM_SMEM_BYTES>>>(
        xt, wqkvT, bqkv, qkv, M, 3 * EE, EE);

    // 2) Causal flash attention -> tf32 y
    attn_mma<<<dim3(TT / 128, HH, BB), 256, ATT_SMEM_BYTES>>>(qkv, y);

    // 3) Output projection -> fp32 out
    gemm_mma_tf32<0><<<dim3(EE / 128, M / 128), 256, GEMM_SMEM_BYTES>>>(
        y, wprojT, bproj, out, M, EE, EE);
}

// round 7
// speedup vs baseline: 3.8767x; 1.0986x over previous
#include <cuda_runtime.h>
#include <math.h>
#include <stdint.h>

// Problem dims (fixed by reference)
#define BB 4
#define TT 2048
#define EE 1024
#define HH 16
#define DD 64

// Scratch (allocation is banned; use __device__ globals)
__device__ float g_qkv[(size_t)BB * TT * 3 * EE];   // [B,T,3E] tf32 bits, Q pre-scaled
__device__ float g_y[(size_t)BB * TT * EE];         // [B,T,E]  tf32 bits
__device__ float g_xt[(size_t)BB * TT * EE];        // x as tf32 bits
__device__ float g_wqkvT[(size_t)3 * EE * EE];      // W_qkv^T, K-major, tf32 bits
__device__ float g_wprojT[(size_t)EE * EE];         // W_proj^T, K-major, tf32 bits

__device__ __forceinline__ uint32_t f2tf32(float f) {
    uint32_t r;
    asm("cvt.rna.tf32.f32 %0, %1;" : "=r"(r) : "f"(f));
    return r;
}

__device__ __forceinline__ void mma_tf32(float c[4], uint32_t a0, uint32_t a1,
                                         uint32_t a2, uint32_t a3,
                                         uint32_t b0, uint32_t b1) {
    asm volatile(
        "mma.sync.aligned.m16n8k8.row.col.f32.tf32.tf32.f32 "
        "{%0,%1,%2,%3}, {%4,%5,%6,%7}, {%8,%9}, {%0,%1,%2,%3};"
        : "+f"(c[0]), "+f"(c[1]), "+f"(c[2]), "+f"(c[3])
        : "r"(a0), "r"(a1), "r"(a2), "r"(a3), "r"(b0), "r"(b1));
}

__device__ __forceinline__ void cp16(float* dst_smem, const float* src) {
    uint32_t d = (uint32_t)__cvta_generic_to_shared(dst_smem);
    asm volatile("cp.async.cg.shared.global [%0], [%1], 16;"
                 :: "r"(d), "l"(src) : "memory");
}
#define CP_COMMIT() asm volatile("cp.async.commit_group;" ::: "memory")
#define CP_WAIT1()  asm volatile("cp.async.wait_group 1;" ::: "memory")

// ---------------------------------------------------------------------------
// x -> tf32 bits (elementwise)
// ---------------------------------------------------------------------------
__global__ __launch_bounds__(256) void cvt_tf32_kernel(
    const float* __restrict__ in, float* __restrict__ out)
{
    const size_t i = ((size_t)blockIdx.x * 256 + threadIdx.x) * 4;
    float4 v = *(const float4*)(in + i);
    uint4 u = make_uint4(f2tf32(v.x), f2tf32(v.y), f2tf32(v.z), f2tf32(v.w));
    *(uint4*)(out + i) = u;
}

// ---------------------------------------------------------------------------
// Transpose + tf32 convert: out[c][r] = tf32(in[r][c])
// ---------------------------------------------------------------------------
__global__ __launch_bounds__(256) void transpose_kernel(
    const float* __restrict__ in, float* __restrict__ out, int R, int C)
{
    __shared__ float t[32][33];
    int x = blockIdx.x * 32 + threadIdx.x;
    int y = blockIdx.y * 32 + threadIdx.y;
#pragma unroll
    for (int j = 0; j < 32; j += 8)
        t[threadIdx.y + j][threadIdx.x] = in[(size_t)(y + j) * C + x];
    __syncthreads();
    x = blockIdx.y * 32 + threadIdx.x;
    y = blockIdx.x * 32 + threadIdx.y;
#pragma unroll
    for (int j = 0; j < 32; j += 8)
        out[(size_t)(y + j) * R + x] =
            __uint_as_float(f2tf32(t[threadIdx.x][threadIdx.y + j]));
}

// ---------------------------------------------------------------------------
// mma.sync tf32 GEMM with cp.async double-buffering, 2 CTAs/SM.
// Inputs A, Bt already hold tf32 bits. C[M,N] = A@Bt^T + bias.
// MODE 0: plain fp32 output. MODE 1: tf32-convert output, scale cols<EE by 1/8.
// ---------------------------------------------------------------------------
#define SMS 36
#define TILE_F (128 * SMS)
#define GEMM_SMEM_BYTES (2 * 2 * TILE_F * 4)

template <int MODE>
__global__ __launch_bounds__(256, 2) void gemm_mma_tf32(
    const float* __restrict__ A, const float* __restrict__ Bt,
    const float* __restrict__ bias, float* __restrict__ C,
    int M, int N, int K)
{
    extern __shared__ float smem[];
    float* As = smem;               // [2][128][SMS]
    float* Bs = smem + 2 * TILE_F;  // [2][128][SMS]

    const int tid  = threadIdx.x;
    const int wid  = tid >> 5;
    const int lane = tid & 31;
    const int wm   = wid >> 2;
    const int wn   = wid & 3;
    const int r1   = lane >> 2;
    const int cg   = lane & 3;
    const int m0   = blockIdx.y << 7;
    const int n0   = blockIdx.x << 7;

    const float* Ap  = A  + (size_t)m0 * K;
    const float* Btp = Bt + (size_t)n0 * K;

    const int lr  = tid >> 3;          // base row, +32 per iter
    const int lc4 = (tid & 7) << 2;    // float col 0..28

    // Prologue: tile 0 -> buffer 0
#pragma unroll
    for (int i = 0; i < 4; ++i) {
        const int r = lr + (i << 5);
        cp16(As + r * SMS + lc4, Ap + (size_t)r * K + lc4);
        cp16(Bs + r * SMS + lc4, Btp + (size_t)r * K + lc4);
    }
    CP_COMMIT();

    float acc[4][4][4] = {};

    const int nT = K >> 5;
    for (int t = 0; t < nT; ++t) {
        const int buf = t & 1;
        if (t + 1 < nT) {
            const int k0 = (t + 1) << 5;
            const int nxt = (t + 1) & 1;
#pragma unroll
            for (int i = 0; i < 4; ++i) {
                const int r = lr + (i << 5);
                cp16(As + nxt * TILE_F + r * SMS + lc4, Ap + (size_t)r * K + k0 + lc4);
                cp16(Bs + nxt * TILE_F + r * SMS + lc4, Btp + (size_t)r * K + k0 + lc4);
            }
        }
        CP_COMMIT();
        CP_WAIT1();
        __syncthreads();

        const float* Ab = As + buf * TILE_F;
        const float* Bb = Bs + buf * TILE_F;
#pragma unroll
        for (int ks = 0; ks < 4; ++ks) {
            const int kk = ks << 3;
            uint32_t bf[4][2];
#pragma unroll
            for (int nt = 0; nt < 4; ++nt) {
                const float* p = Bb + (wn * 32 + nt * 8 + r1) * SMS + kk + cg;
                bf[nt][0] = __float_as_uint(p[0]);
                bf[nt][1] = __float_as_uint(p[4]);
            }
#pragma unroll
            for (int mt = 0; mt < 4; ++mt) {
                const float* p = Ab + (wm * 64 + mt * 16 + r1) * SMS + kk + cg;
                uint32_t a0 = __float_as_uint(p[0]);
                uint32_t a1 = __float_as_uint(p[8 * SMS]);
                uint32_t a2 = __float_as_uint(p[4]);
                uint32_t a3 = __float_as_uint(p[8 * SMS + 4]);
#pragma unroll
                for (int nt = 0; nt < 4; ++nt)
                    mma_tf32(acc[mt][nt], a0, a1, a2, a3, bf[nt][0], bf[nt][1]);
            }
        }
        __syncthreads();
    }

    // Epilogue
#pragma unroll
    for (int mt = 0; mt < 4; ++mt) {
#pragma unroll
        for (int nt = 0; nt < 4; ++nt) {
            const int row = m0 + wm * 64 + mt * 16 + r1;
            const int col = n0 + wn * 32 + nt * 8 + 2 * cg;
            const float2 bv = *(const float2*)(bias + col);
            float v[4];
            v[0] = acc[mt][nt][0] + bv.x;
            v[1] = acc[mt][nt][1] + bv.y;
            v[2] = acc[mt][nt][2] + bv.x;
            v[3] = acc[mt][nt][3] + bv.y;
            if (MODE == 1) {
                const float sc = (col < EE) ? 0.125f : 1.0f; // Q cols pre-scaled
#pragma unroll
                for (int q = 0; q < 4; ++q)
                    v[q] = __uint_as_float(f2tf32(v[q] * sc));
            }
            *(float2*)(C + (size_t)row * N + col) = make_float2(v[0], v[1]);
            *(float2*)(C + (size_t)(row + 8) * N + col) = make_float2(v[2], v[3]);
        }
    }
}

// ---------------------------------------------------------------------------
// Tensor-core flash attention (causal), mma.sync tf32 + cp.async double buffer.
// qkv holds tf32 bits with Q pre-scaled. CTA: 128 queries, 8 warps.
// Key tiles of 64; K rows 0-63 and V rows 64-127 of each buffer.
// ---------------------------------------------------------------------------
#define AST 68                           // smem row stride (floats)
#define ATT_SMEM_FLOATS (2 * 128 * AST + 8 * 16 * AST)
#define ATT_SMEM_BYTES (ATT_SMEM_FLOATS * 4)

__global__ __launch_bounds__(256, 2) void attn_mma(
    const float* __restrict__ qkv, float* __restrict__ y)
{
    extern __shared__ float sm[];
    float* Pw = sm + 2 * 128 * AST;      // [8][16][AST]

    const int tid  = threadIdx.x;
    const int wid  = tid >> 5;
    const int lane = tid & 31;
    const int r1   = lane >> 2;
    const int cg   = lane & 3;
    const int q0   = blockIdx.x << 7;
    const int h    = blockIdx.y;
    const int b    = blockIdx.z;
    const int qw   = q0 + (wid << 4);

    const size_t rs = (size_t)3 * EE;
    const float* base = qkv + (size_t)(b * TT) * rs + h * DD;

    // ---- Stage Q (already scaled tf32 bits) into sm[0 .. 128*AST) ----
#pragma unroll
    for (int i = 0; i < 8; ++i) {
        const int idx = tid + (i << 8);
        const int row = idx >> 4;
        const int d4  = (idx & 15) << 2;
        *(float4*)(sm + row * AST + d4) =
            *(const float4*)(base + (size_t)(q0 + row) * rs + d4);
    }
    __syncthreads();

    uint32_t qf[8][4];
#pragma unroll
    for (int ks = 0; ks < 8; ++ks) {
        const float* p = sm + ((wid << 4) + r1) * AST + (ks << 3) + cg;
        qf[ks][0] = __float_as_uint(p[0]);
        qf[ks][1] = __float_as_uint(p[8 * AST]);
        qf[ks][2] = __float_as_uint(p[4]);
        qf[ks][3] = __float_as_uint(p[8 * AST + 4]);
    }
    __syncthreads();

    const int nkb = (q0 >> 6) + 2;

    // staging indices: 256 threads x 4 iters cover 64 rows x 16 float4
    const int srow = tid >> 4;          // 0..15, +16 per iter
    const int sd4  = (tid & 15) << 2;   // 0..60

    // Prologue: tile 0 -> buffer 0
#pragma unroll
    for (int i = 0; i < 4; ++i) {
        const int row = srow + (i << 4);
        const float* kp = base + (size_t)row * rs + EE + sd4;
        const float* vp = base + (size_t)row * rs + 2 * EE + sd4;
        cp16(sm + row * AST + sd4, kp);
        cp16(sm + (64 + row) * AST + sd4, vp);
    }
    CP_COMMIT();

    float o[8][4] = {};
    float m0r = -INFINITY, m1r = -INFINITY;
    float l0r = 0.f, l1r = 0.f;

    for (int kb = 0; kb < nkb; ++kb) {
        const int buf = kb & 1;
        if (kb + 1 < nkb) {
            const int k0n = (kb + 1) << 6;
            float* nb = sm + ((kb + 1) & 1) * 128 * AST;
#pragma unroll
            for (int i = 0; i < 4; ++i) {
                const int row = srow + (i << 4);
                const float* kp = base + (size_t)(k0n + row) * rs + EE + sd4;
                const float* vp = base + (size_t)(k0n + row) * rs + 2 * EE + sd4;
                cp16(nb + row * AST + sd4, kp);
                cp16(nb + (64 + row) * AST + sd4, vp);
            }
        }
        CP_COMMIT();
        CP_WAIT1();
        __syncthreads();

        const int k0 = kb << 6;
        const float* Ks = sm + buf * 128 * AST;
        const float* Vs = Ks + 64 * AST;

        if (k0 <= qw + 15) {
            // ---- S = Qs @ K^T ----
            float s[8][4] = {};
#pragma unroll
            for (int ks = 0; ks < 8; ++ks) {
#pragma unroll
                for (int nt = 0; nt < 8; ++nt) {
                    const float* p = Ks + ((nt << 3) + r1) * AST + (ks << 3) + cg;
                    mma_tf32(s[nt], qf[ks][0], qf[ks][1], qf[ks][2], qf[ks][3],
                             __float_as_uint(p[0]), __float_as_uint(p[4]));
                }
            }

            // ---- Causal mask ----
            if (k0 + 63 > qw) {
                const int row0 = qw + r1, row1 = row0 + 8;
#pragma unroll
                for (int nt = 0; nt < 8; ++nt) {
                    const int col = k0 + (nt << 3) + 2 * cg;
                    if (col > row0)     s[nt][0] = -1e30f;
                    if (col + 1 > row0) s[nt][1] = -1e30f;
                    if (col > row1)     s[nt][2] = -1e30f;
                    if (col + 1 > row1) s[nt][3] = -1e30f;
                }
            }

            // ---- Online softmax ----
            float mx0 = -INFINITY, mx1 = -INFINITY;
#pragma unroll
            for (int nt = 0; nt < 8; ++nt) {
                mx0 = fmaxf(mx0, fmaxf(s[nt][0], s[nt][1]));
                mx1 = fmaxf(mx1, fmaxf(s[nt][2], s[nt][3]));
            }
            mx0 = fmaxf(mx0, __shfl_xor_sync(0xffffffffu, mx0, 1));
            mx0 = fmaxf(mx0, __shfl_xor_sync(0xffffffffu, mx0, 2));
            mx1 = fmaxf(mx1, __shfl_xor_sync(0xffffffffu, mx1, 1));
            mx1 = fmaxf(mx1, __shfl_xor_sync(0xffffffffu, mx1, 2));

            const float mn0 = fmaxf(m0r, mx0);
            const float mn1 = fmaxf(m1r, mx1);
            const float c0 = __expf(m0r - mn0);
            const float c1 = __expf(m1r - mn1);
            m0r = mn0; m1r = mn1;

            float sum0 = 0.f, sum1 = 0.f;
#pragma unroll
            for (int nt = 0; nt < 8; ++nt) {
                s[nt][0] = __expf(s[nt][0] - mn0);
                s[nt][1] = __expf(s[nt][1] - mn0);
                s[nt][2] = __expf(s[nt][2] - mn1);
                s[nt][3] = __expf(s[nt][3] - mn1);
                sum0 += s[nt][0] + s[nt][1];
                sum1 += s[nt][2] + s[nt][3];
            }
            sum0 += __shfl_xor_sync(0xffffffffu, sum0, 1);
            sum0 += __shfl_xor_sync(0xffffffffu, sum0, 2);
            sum1 += __shfl_xor_sync(0xffffffffu, sum1, 1);
            sum1 += __shfl_xor_sync(0xffffffffu, sum1, 2);
            l0r = l0r * c0 + sum0;
            l1r = l1r * c1 + sum1;

#pragma unroll
            for (int nt = 0; nt < 8; ++nt) {
                o[nt][0] *= c0; o[nt][1] *= c0;
                o[nt][2] *= c1; o[nt][3] *= c1;
            }

            // ---- P -> per-warp smem strip (tf32 bits) ----
            float* pw = Pw + wid * 16 * AST;
#pragma unroll
            for (int nt = 0; nt < 8; ++nt) {
                float2 p01, p23;
                p01.x = __uint_as_float(f2tf32(s[nt][0]));
                p01.y = __uint_as_float(f2tf32(s[nt][1]));
                p23.x = __uint_as_float(f2tf32(s[nt][2]));
                p23.y = __uint_as_float(f2tf32(s[nt][3]));
                *(float2*)(pw + r1 * AST + (nt << 3) + 2 * cg) = p01;
                *(float2*)(pw + (r1 + 8) * AST + (nt << 3) + 2 * cg) = p23;
            }
            __syncwarp();

            // ---- O += P @ V ----
#pragma unroll
            for (int ks = 0; ks < 8; ++ks) {
                const float* pa = pw + r1 * AST + (ks << 3) + cg;
                const uint32_t a0 = __float_as_uint(pa[0]);
                const uint32_t a1 = __float_as_uint(pa[8 * AST]);
                const uint32_t a2 = __float_as_uint(pa[4]);
                const uint32_t a3 = __float_as_uint(pa[8 * AST + 4]);
#pragma unroll
                for (int nt = 0; nt < 8; ++nt) {
                    const float* pv = Vs + ((ks << 3) + cg) * AST + (nt << 3) + r1;
                    mma_tf32(o[nt], a0, a1, a2, a3,
                             __float_as_uint(pv[0]), __float_as_uint(pv[4 * AST]));
                }
            }
            __syncwarp();
        }
        __syncthreads();
    }

    // ---- Normalize + write (tf32 bits; y feeds proj GEMM only) ----
    const float inv0 = 1.0f / l0r;
    const float inv1 = 1.0f / l1r;
    const size_t row0 = (size_t)(b * TT + qw + r1);
#pragma unroll
    for (int nt = 0; nt < 8; ++nt) {
        const int col = h * DD + (nt << 3) + 2 * cg;
        float2 o0, o1;
        o0.x = __uint_as_float(f2tf32(o[nt][0] * inv0));
        o0.y = __uint_as_float(f2tf32(o[nt][1] * inv0));
        o1.x = __uint_as_float(f2tf32(o[nt][2] * inv1));
        o1.y = __uint_as_float(f2tf32(o[nt][3] * inv1));
        *(float2*)(y + row0 * EE + col) = o0;
        *(float2*)(y + (row0 + 8) * EE + col) = o1;
    }
}

// ---------------------------------------------------------------------------
// Launch
// ---------------------------------------------------------------------------
extern "C" void kernel_launch(void* const* d_in, const int* in_sizes, int n_in,
                              void* d_out, int out_size)
{
    const float* x     = (const float*)d_in[0];
    const float* Wqkv  = (const float*)d_in[1];
    const float* bqkv  = (const float*)d_in[2];
    const float* Wproj = (const float*)d_in[3];
    const float* bproj = (const float*)d_in[4];
    float* out = (float*)d_out;

    float *qkv, *y, *xt, *wqkvT, *wprojT;
    cudaGetSymbolAddress((void**)&qkv, g_qkv);
    cudaGetSymbolAddress((void**)&y, g_y);
    cudaGetSymbolAddress((void**)&xt, g_xt);
    cudaGetSymbolAddress((void**)&wqkvT, g_wqkvT);
    cudaGetSymbolAddress((void**)&wprojT, g_wprojT);

    cudaFuncSetAttribute(gemm_mma_tf32<0>,
                         cudaFuncAttributeMaxDynamicSharedMemorySize, GEMM_SMEM_BYTES);
    cudaFuncSetAttribute(gemm_mma_tf32<1>,
                         cudaFuncAttributeMaxDynamicSharedMemorySize, GEMM_SMEM_BYTES);
    cudaFuncSetAttribute(attn_mma,
                         cudaFuncAttributeMaxDynamicSharedMemorySize, ATT_SMEM_BYTES);

    const int M = BB * TT;

    // 0) Pre-convert inputs: x -> tf32, W^T -> tf32 K-major
    cvt_tf32_kernel<<<(M * EE) / (256 * 4), 256>>>(x, xt);
    transpose_kernel<<<dim3(3 * EE / 32, EE / 32), dim3(32, 8)>>>(Wqkv, wqkvT, EE, 3 * EE);
    transpose_kernel<<<dim3(EE / 32, EE / 32), dim3(32, 8)>>>(Wproj, wprojT, EE, EE);

    // 1) QKV projection -> tf32 qkv with Q pre-scaled
    gemm_mma_tf32<1><<<dim3(3 * EE / 128, M / 128), 256, GEMM_SMEM_BYTES>>>(
        xt, wqkvT, bqkv, qkv, M, 3 * EE, EE);

    // 2) Causal flash attention -> tf32 y
    attn_mma<<<dim3(TT / 128, HH, BB), 256, ATT_SMEM_BYTES>>>(qkv, y);

    // 3) Output projection -> fp32 out
    gemm_mma_tf32<0><<<dim3(EE / 128, M / 128), 256, GEMM_SMEM_BYTES>>>(
        y, wprojT, bproj, out, M, EE, EE);
}

// round 8
// speedup vs baseline: 4.5315x; 1.1689x over previous
#include <cuda_runtime.h>
#include <math.h>
#include <stdint.h>

// Problem dims (fixed by reference)
#define BB 4
#define TT 2048
#define EE 1024
#define HH 16
#define DD 64

// All tf32 K-major operand buffers use sigma-interleaved k-groups of 8:
//   mem position of actual k (within 8-group): sigma(k) = ((k&3)<<1) | (k>>2)
// so an mma A/B fragment's k-slots (cg, cg+4) sit at contiguous (2cg, 2cg+1).

// Scratch (allocation is banned; use __device__ globals)
__device__ float g_qkv[(size_t)BB * TT * 3 * EE];   // [B,T,3E] tf32 bits, sigma'd cols, Q pre-scaled
__device__ float g_y[(size_t)BB * TT * EE];         // [B,T,E]  tf32 bits, sigma'd (inherited)
__device__ float g_xt[(size_t)BB * TT * EE];        // x tf32 bits, sigma'd along E
__device__ float g_wqkvT[(size_t)3 * EE * EE];      // W_qkv^T K-major, tf32, sigma'd K
__device__ float g_wprojT[(size_t)EE * EE];         // W_proj^T K-major, tf32, sigma'd K

__device__ __forceinline__ uint32_t f2tf32(float f) {
    uint32_t r;
    asm("cvt.rna.tf32.f32 %0, %1;" : "=r"(r) : "f"(f));
    return r;
}

__device__ __forceinline__ void mma_tf32(float c[4], uint32_t a0, uint32_t a1,
                                         uint32_t a2, uint32_t a3,
                                         uint32_t b0, uint32_t b1) {
    asm volatile(
        "mma.sync.aligned.m16n8k8.row.col.f32.tf32.tf32.f32 "
        "{%0,%1,%2,%3}, {%4,%5,%6,%7}, {%8,%9}, {%0,%1,%2,%3};"
        : "+f"(c[0]), "+f"(c[1]), "+f"(c[2]), "+f"(c[3])
        : "r"(a0), "r"(a1), "r"(a2), "r"(a3), "r"(b0), "r"(b1));
}

__device__ __forceinline__ void cp16(float* dst_smem, const float* src) {
    uint32_t d = (uint32_t)__cvta_generic_to_shared(dst_smem);
    asm volatile("cp.async.cg.shared.global [%0], [%1], 16;"
                 :: "r"(d), "l"(src) : "memory");
}
#define CP_COMMIT() asm volatile("cp.async.commit_group;" ::: "memory")
#define CP_WAIT1()  asm volatile("cp.async.wait_group 1;" ::: "memory")

// ---------------------------------------------------------------------------
// x -> tf32 bits, sigma-interleaved per 8 (8 elements per thread)
// ---------------------------------------------------------------------------
__global__ __launch_bounds__(256) void cvt_tf32_kernel(
    const float* __restrict__ in, float* __restrict__ out)
{
    const size_t i = ((size_t)blockIdx.x * 256 + threadIdx.x) * 8;
    float4 v0 = *(const float4*)(in + i);
    float4 v1 = *(const float4*)(in + i + 4);
    uint4 u0, u1;
    u0.x = f2tf32(v0.x); u0.y = f2tf32(v1.x); u0.z = f2tf32(v0.y); u0.w = f2tf32(v1.y);
    u1.x = f2tf32(v0.z); u1.y = f2tf32(v1.z); u1.z = f2tf32(v0.w); u1.w = f2tf32(v1.w);
    *(uint4*)(out + i) = u0;
    *(uint4*)(out + i + 4) = u1;
}

// ---------------------------------------------------------------------------
// Transpose + tf32 + sigma on output K dim: out[c][sig(r)] = tf32(in[r][c])
// ---------------------------------------------------------------------------
__global__ __launch_bounds__(256) void transpose_kernel(
    const float* __restrict__ in, float* __restrict__ out, int R, int C)
{
    __shared__ float t[32][33];
    int x = blockIdx.x * 32 + threadIdx.x;
    int y = blockIdx.y * 32 + threadIdx.y;
#pragma unroll
    for (int j = 0; j < 32; j += 8)
        t[threadIdx.y + j][threadIdx.x] = in[(size_t)(y + j) * C + x];
    __syncthreads();
    const int sx = (threadIdx.x & ~7) |
                   (((threadIdx.x & 3) << 1) | ((threadIdx.x >> 2) & 1));
    x = blockIdx.y * 32 + sx;
    y = blockIdx.x * 32 + threadIdx.y;
#pragma unroll
    for (int j = 0; j < 32; j += 8)
        out[(size_t)(y + j) * R + x] =
            __uint_as_float(f2tf32(t[threadIdx.x][threadIdx.y + j]));
}

// ---------------------------------------------------------------------------
// mma.sync tf32 GEMM, sigma-layout operands, vectorized frag loads,
// cp.async double buffer, 2 CTAs/SM.
// MODE 0: plain fp32 output. MODE 1: tf32 output with sigma'd cols; cols<EE *1/8.
// ---------------------------------------------------------------------------
#define SMS 40
#define TILE_F (128 * SMS)
#define GEMM_SMEM_BYTES (2 * 2 * TILE_F * 4)

template <int MODE>
__global__ __launch_bounds__(256, 2) void gemm_mma_tf32(
    const float* __restrict__ A, const float* __restrict__ Bt,
    const float* __restrict__ bias, float* __restrict__ C,
    int M, int N, int K)
{
    extern __shared__ float smem[];
    float* As = smem;               // [2][128][SMS]
    float* Bs = smem + 2 * TILE_F;  // [2][128][SMS]

    const int tid  = threadIdx.x;
    const int wid  = tid >> 5;
    const int lane = tid & 31;
    const int wm   = wid >> 2;
    const int wn   = wid & 3;
    const int r1   = lane >> 2;
    const int cg   = lane & 3;
    const int m0   = blockIdx.y << 7;
    const int n0   = blockIdx.x << 7;

    const float* Ap  = A  + (size_t)m0 * K;
    const float* Btp = Bt + (size_t)n0 * K;

    const int lr  = tid >> 3;          // base row, +32 per iter
    const int lc4 = (tid & 7) << 2;    // float col 0..28

    // Prologue: tile 0 -> buffer 0
#pragma unroll
    for (int i = 0; i < 4; ++i) {
        const int r = lr + (i << 5);
        cp16(As + r * SMS + lc4, Ap + (size_t)r * K + lc4);
        cp16(Bs + r * SMS + lc4, Btp + (size_t)r * K + lc4);
    }
    CP_COMMIT();

    float acc[4][4][4] = {};

    const int nT = K >> 5;
    for (int t = 0; t < nT; ++t) {
        const int buf = t & 1;
        if (t + 1 < nT) {
            const int k0 = (t + 1) << 5;
            const int nxt = (t + 1) & 1;
#pragma unroll
            for (int i = 0; i < 4; ++i) {
                const int r = lr + (i << 5);
                cp16(As + nxt * TILE_F + r * SMS + lc4, Ap + (size_t)r * K + k0 + lc4);
                cp16(Bs + nxt * TILE_F + r * SMS + lc4, Btp + (size_t)r * K + k0 + lc4);
            }
        }
        CP_COMMIT();
        CP_WAIT1();
        __syncthreads();

        const float* Ab = As + buf * TILE_F;
        const float* Bb = Bs + buf * TILE_F;
#pragma unroll
        for (int ks = 0; ks < 4; ++ks) {
            const int kk = (ks << 3) + (cg << 1);
            uint32_t bf[4][2];
#pragma unroll
            for (int nt = 0; nt < 4; ++nt) {
                const float2 bp =
                    *(const float2*)(Bb + (wn * 32 + nt * 8 + r1) * SMS + kk);
                bf[nt][0] = __float_as_uint(bp.x);
                bf[nt][1] = __float_as_uint(bp.y);
            }
#pragma unroll
            for (int mt = 0; mt < 4; ++mt) {
                const float* p = Ab + (wm * 64 + mt * 16 + r1) * SMS + kk;
                const float2 alo = *(const float2*)(p);
                const float2 ahi = *(const float2*)(p + 8 * SMS);
                const uint32_t a0 = __float_as_uint(alo.x);
                const uint32_t a1 = __float_as_uint(ahi.x);
                const uint32_t a2 = __float_as_uint(alo.y);
                const uint32_t a3 = __float_as_uint(ahi.y);
#pragma unroll
                for (int nt = 0; nt < 4; ++nt)
                    mma_tf32(acc[mt][nt], a0, a1, a2, a3, bf[nt][0], bf[nt][1]);
            }
        }
        __syncthreads();
    }

    // Epilogue
    const int mo = ((cg & 1) << 2) | (cg >> 1);   // sigma(2*cg)
#pragma unroll
    for (int mt = 0; mt < 4; ++mt) {
#pragma unroll
        for (int nt = 0; nt < 4; ++nt) {
            const int row  = m0 + wm * 64 + mt * 16 + r1;
            const int colb = n0 + wn * 32 + nt * 8;
            const float2 bv = *(const float2*)(bias + colb + 2 * cg);
            float v[4];
            v[0] = acc[mt][nt][0] + bv.x;
            v[1] = acc[mt][nt][1] + bv.y;
            v[2] = acc[mt][nt][2] + bv.x;
            v[3] = acc[mt][nt][3] + bv.y;
            if (MODE == 1) {
                const float sc = (colb < EE) ? 0.125f : 1.0f; // Q cols pre-scaled
#pragma unroll
                for (int q = 0; q < 4; ++q)
                    v[q] = __uint_as_float(f2tf32(v[q] * sc));
                // sigma'd column positions: 2cg -> mo, 2cg+1 -> mo+2
                C[(size_t)row * N + colb + mo]           = v[0];
                C[(size_t)row * N + colb + mo + 2]       = v[1];
                C[(size_t)(row + 8) * N + colb + mo]     = v[2];
                C[(size_t)(row + 8) * N + colb + mo + 2] = v[3];
            } else {
                *(float2*)(C + (size_t)row * N + colb + 2 * cg) =
                    make_float2(v[0], v[1]);
                *(float2*)(C + (size_t)(row + 8) * N + colb + 2 * cg) =
                    make_float2(v[2], v[3]);
            }
        }
    }
}

// ---------------------------------------------------------------------------
// Tensor-core flash attention (causal), sigma-layout qkv, cp.async double buf.
// CTA: 128 queries, 8 warps. Key tiles of 64 (K rows 0-63, V rows 64-127).
// y written naturally -> inherits sigma layout from V's sigma'd d-columns.
// ---------------------------------------------------------------------------
#define AST 72                           // K/V smem row stride (floats)
#define PST 68                           // P strip row stride (floats)
#define ATT_SMEM_FLOATS (2 * 128 * AST + 8 * 16 * PST)
#define ATT_SMEM_BYTES (ATT_SMEM_FLOATS * 4)

__global__ __launch_bounds__(256, 2) void attn_mma(
    const float* __restrict__ qkv, float* __restrict__ y)
{
    extern __shared__ float sm[];
    float* Pw = sm + 2 * 128 * AST;      // [8][16][PST]

    const int tid  = threadIdx.x;
    const int wid  = tid >> 5;
    const int lane = tid & 31;
    const int r1   = lane >> 2;
    const int cg   = lane & 3;
    const int q0   = blockIdx.x << 7;
    const int h    = blockIdx.y;
    const int b    = blockIdx.z;
    const int qw   = q0 + (wid << 4);

    const size_t rs = (size_t)3 * EE;
    const float* base = qkv + (size_t)(b * TT) * rs + h * DD;

    // ---- Stage Q (scaled, sigma'd tf32 bits) into sm[0 .. 128*AST) ----
#pragma unroll
    for (int i = 0; i < 8; ++i) {
        const int idx = tid + (i << 8);
        const int row = idx >> 4;
        const int d4  = (idx & 15) << 2;
        *(float4*)(sm + row * AST + d4) =
            *(const float4*)(base + (size_t)(q0 + row) * rs + d4);
    }
    __syncthreads();

    uint32_t qf[8][4];
#pragma unroll
    for (int ks = 0; ks < 8; ++ks) {
        const float* p = sm + ((wid << 4) + r1) * AST + (ks << 3) + (cg << 1);
        const float2 lo = *(const float2*)(p);
        const float2 hi = *(const float2*)(p + 8 * AST);
        qf[ks][0] = __float_as_uint(lo.x);
        qf[ks][1] = __float_as_uint(hi.x);
        qf[ks][2] = __float_as_uint(lo.y);
        qf[ks][3] = __float_as_uint(hi.y);
    }
    __syncthreads();

    const int nkb = (q0 >> 6) + 2;

    const int srow = tid >> 4;          // 0..15, +16 per iter
    const int sd4  = (tid & 15) << 2;   // 0..60

    // Prologue: tile 0 -> buffer 0
#pragma unroll
    for (int i = 0; i < 4; ++i) {
        const int row = srow + (i << 4);
        cp16(sm + row * AST + sd4,        base + (size_t)row * rs + EE + sd4);
        cp16(sm + (64 + row) * AST + sd4, base + (size_t)row * rs + 2 * EE + sd4);
    }
    CP_COMMIT();

    float o[8][4] = {};
    float m0r = -INFINITY, m1r = -INFINITY;
    float l0r = 0.f, l1r = 0.f;

    for (int kb = 0; kb < nkb; ++kb) {
        const int buf = kb & 1;
        if (kb + 1 < nkb) {
            const int k0n = (kb + 1) << 6;
            float* nb = sm + ((kb + 1) & 1) * 128 * AST;
#pragma unroll
            for (int i = 0; i < 4; ++i) {
                const int row = srow + (i << 4);
                cp16(nb + row * AST + sd4,
                     base + (size_t)(k0n + row) * rs + EE + sd4);
                cp16(nb + (64 + row) * AST + sd4,
                     base + (size_t)(k0n + row) * rs + 2 * EE + sd4);
            }
        }
        CP_COMMIT();
        CP_WAIT1();
        __syncthreads();

        const int k0 = kb << 6;
        const float* Ks = sm + buf * 128 * AST;
        const float* Vs = Ks + 64 * AST;

        if (k0 <= qw + 15) {
            // ---- S = Qs @ K^T ----
            float s[8][4] = {};
#pragma unroll
            for (int ks = 0; ks < 8; ++ks) {
#pragma unroll
                for (int nt = 0; nt < 8; ++nt) {
                    const float2 bp = *(const float2*)(
                        Ks + ((nt << 3) + r1) * AST + (ks << 3) + (cg << 1));
                    mma_tf32(s[nt], qf[ks][0], qf[ks][1], qf[ks][2], qf[ks][3],
                             __float_as_uint(bp.x), __float_as_uint(bp.y));
                }
            }

            // ---- Causal mask ----
            if (k0 + 63 > qw) {
                const int row0 = qw + r1, row1 = row0 + 8;
#pragma unroll
                for (int nt = 0; nt < 8; ++nt) {
                    const int col = k0 + (nt << 3) + 2 * cg;
                    if (col > row0)     s[nt][0] = -1e30f;
                    if (col + 1 > row0) s[nt][1] = -1e30f;
                    if (col > row1)     s[nt][2] = -1e30f;
                    if (col + 1 > row1) s[nt][3] = -1e30f;
                }
            }

            // ---- Online softmax ----
            float mx0 = -INFINITY, mx1 = -INFINITY;
#pragma unroll
            for (int nt = 0; nt < 8; ++nt) {
                mx0 = fmaxf(mx0, fmaxf(s[nt][0], s[nt][1]));
                mx1 = fmaxf(mx1, fmaxf(s[nt][2], s[nt][3]));
            }
            mx0 = fmaxf(mx0, __shfl_xor_sync(0xffffffffu, mx0, 1));
            mx0 = fmaxf(mx0, __shfl_xor_sync(0xffffffffu, mx0, 2));
            mx1 = fmaxf(mx1, __shfl_xor_sync(0xffffffffu, mx1, 1));
            mx1 = fmaxf(mx1, __shfl_xor_sync(0xffffffffu, mx1, 2));

            const float mn0 = fmaxf(m0r, mx0);
            const float mn1 = fmaxf(m1r, mx1);
            const float c0 = __expf(m0r - mn0);
            const float c1 = __expf(m1r - mn1);
            m0r = mn0; m1r = mn1;

            float sum0 = 0.f, sum1 = 0.f;
#pragma unroll
            for (int nt = 0; nt < 8; ++nt) {
                s[nt][0] = __expf(s[nt][0] - mn0);
                s[nt][1] = __expf(s[nt][1] - mn0);
                s[nt][2] = __expf(s[nt][2] - mn1);
                s[nt][3] = __expf(s[nt][3] - mn1);
                sum0 += s[nt][0] + s[nt][1];
                sum1 += s[nt][2] + s[nt][3];
            }
            sum0 += __shfl_xor_sync(0xffffffffu, sum0, 1);
            sum0 += __shfl_xor_sync(0xffffffffu, sum0, 2);
            sum1 += __shfl_xor_sync(0xffffffffu, sum1, 1);
            sum1 += __shfl_xor_sync(0xffffffffu, sum1, 2);
            l0r = l0r * c0 + sum0;
            l1r = l1r * c1 + sum1;

#pragma unroll
            for (int nt = 0; nt < 8; ++nt) {
                o[nt][0] *= c0; o[nt][1] *= c0;
                o[nt][2] *= c1; o[nt][3] *= c1;
            }

            // ---- P -> per-warp smem strip (natural layout, tf32 bits) ----
            float* pw = Pw + wid * 16 * PST;
#pragma unroll
            for (int nt = 0; nt < 8; ++nt) {
                float2 p01, p23;
                p01.x = __uint_as_float(f2tf32(s[nt][0]));
                p01.y = __uint_as_float(f2tf32(s[nt][1]));
                p23.x = __uint_as_float(f2tf32(s[nt][2]));
                p23.y = __uint_as_float(f2tf32(s[nt][3]));
                *(float2*)(pw + r1 * PST + (nt << 3) + 2 * cg) = p01;
                *(float2*)(pw + (r1 + 8) * PST + (nt << 3) + 2 * cg) = p23;
            }
            __syncwarp();

            // ---- O += P @ V ----
#pragma unroll
            for (int ks = 0; ks < 8; ++ks) {
                const float* pa = pw + r1 * PST + (ks << 3) + cg;
                const uint32_t a0 = __float_as_uint(pa[0]);
                const uint32_t a1 = __float_as_uint(pa[8 * PST]);
                const uint32_t a2 = __float_as_uint(pa[4]);
                const uint32_t a3 = __float_as_uint(pa[8 * PST + 4]);
#pragma unroll
                for (int nt = 0; nt < 8; ++nt) {
                    const float* pv = Vs + ((ks << 3) + cg) * AST + (nt << 3) + r1;
                    mma_tf32(o[nt], a0, a1, a2, a3,
                             __float_as_uint(pv[0]), __float_as_uint(pv[4 * AST]));
                }
            }
            __syncwarp();
        }
        __syncthreads();
    }

    // ---- Normalize + write (natural positions -> y inherits sigma layout) ----
    const float inv0 = 1.0f / l0r;
    const float inv1 = 1.0f / l1r;
    const size_t row0 = (size_t)(b * TT + qw + r1);
#pragma unroll
    for (int nt = 0; nt < 8; ++nt) {
        const int col = h * DD + (nt << 3) + 2 * cg;
        float2 o0, o1;
        o0.x = __uint_as_float(f2tf32(o[nt][0] * inv0));
        o0.y = __uint_as_float(f2tf32(o[nt][1] * inv0));
        o1.x = __uint_as_float(f2tf32(o[nt][2] * inv1));
        o1.y = __uint_as_float(f2tf32(o[nt][3] * inv1));
        *(float2*)(y + row0 * EE + col) = o0;
        *(float2*)(y + (row0 + 8) * EE + col) = o1;
    }
}

// ---------------------------------------------------------------------------
// Launch
// ---------------------------------------------------------------------------
extern "C" void kernel_launch(void* const* d_in, const int* in_sizes, int n_in,
                              void* d_out, int out_size)
{
    const float* x     = (const float*)d_in[0];
    const float* Wqkv  = (const float*)d_in[1];
    const float* bqkv  = (const float*)d_in[2];
    const float* Wproj = (const float*)d_in[3];
    const float* bproj = (const float*)d_in[4];
    float* out = (float*)d_out;

    float *qkv, *y, *xt, *wqkvT, *wprojT;
    cudaGetSymbolAddress((void**)&qkv, g_qkv);
    cudaGetSymbolAddress((void**)&y, g_y);
    cudaGetSymbolAddress((void**)&xt, g_xt);
    cudaGetSymbolAddress((void**)&wqkvT, g_wqkvT);
    cudaGetSymbolAddress((void**)&wprojT, g_wprojT);

    cudaFuncSetAttribute(gemm_mma_tf32<0>,
                         cudaFuncAttributeMaxDynamicSharedMemorySize, GEMM_SMEM_BYTES);
    cudaFuncSetAttribute(gemm_mma_tf32<1>,
                         cudaFuncAttributeMaxDynamicSharedMemorySize, GEMM_SMEM_BYTES);
    cudaFuncSetAttribute(attn_mma,
                         cudaFuncAttributeMaxDynamicSharedMemorySize, ATT_SMEM_BYTES);

    const int M = BB * TT;

    // 0) Pre-convert inputs: x -> tf32 sigma'd, W^T -> tf32 K-major sigma'd
    cvt_tf32_kernel<<<(M * EE) / (256 * 8), 256>>>(x, xt);
    transpose_kernel<<<dim3(3 * EE / 32, EE / 32), dim3(32, 8)>>>(Wqkv, wqkvT, EE, 3 * EE);
    transpose_kernel<<<dim3(EE / 32, EE / 32), dim3(32, 8)>>>(Wproj, wprojT, EE, EE);

    // 1) QKV projection -> tf32 qkv (sigma'd cols, Q pre-scaled)
    gemm_mma_tf32<1><<<dim3(3 * EE / 128, M / 128), 256, GEMM_SMEM_BYTES>>>(
        xt, wqkvT, bqkv, qkv, M, 3 * EE, EE);

    // 2) Causal flash attention -> tf32 y (sigma layout inherited)
    attn_mma<<<dim3(TT / 128, HH, BB), 256, ATT_SMEM_BYTES>>>(qkv, y);

    // 3) Output projection -> fp32 out
    gemm_mma_tf32<0><<<dim3(EE / 128, M / 128), 256, GEMM_SMEM_BYTES>>>(
        y, wprojT, bproj, out, M, EE, EE);
}